// round 1
// baseline (speedup 1.0000x reference)
#include <cuda_runtime.h>
#include <math.h>

#define DMODEL 3072
#define NHEAD  24
#define HD     128
#define LQ     1280     // 256 txt + 1024 img queries
#define SKV    4352     // 256 txt + 1024 den + 3072 cached
#define STXT   256

// ---------------- scratch (device globals: allocation-free) ----------------
__device__ float g_Q[(size_t)LQ  * DMODEL];
__device__ float g_K[(size_t)SKV * DMODEL];
__device__ float g_V[(size_t)SKV * DMODEL];
__device__ float g_O[(size_t)LQ  * DMODEL];

// ---------------- SGEMM: C[M x 3072] = A[M x 3072] @ W[3072 x 3072] + bias --
// BM=BN=128, BK=8, 256 threads, 8x8 per-thread tile
__global__ __launch_bounds__(256) void sgemm_bias(
    const float* __restrict__ A, const float* __restrict__ W,
    const float* __restrict__ bias, float* __restrict__ C)
{
    __shared__ float As[8][128];
    __shared__ float Ws[8][128];
    const int t  = threadIdx.x;
    const int ty = t >> 4;        // 0..15
    const int tx = t & 15;        // 0..15
    const int m0 = blockIdx.y * 128;
    const int n0 = blockIdx.x * 128;

    float acc[8][8];
#pragma unroll
    for (int i = 0; i < 8; i++)
#pragma unroll
        for (int j = 0; j < 8; j++) acc[i][j] = 0.f;

    const int ar = t >> 1;          // 0..127
    const int ac = (t & 1) * 4;     // 0 / 4
    const int wr = t >> 5;          // 0..7
    const int wc = (t & 31) * 4;    // 0..124

    for (int k0 = 0; k0 < DMODEL; k0 += 8) {
        float4 av = *(const float4*)(A + (size_t)(m0 + ar) * DMODEL + k0 + ac);
        float4 wv = *(const float4*)(W + (size_t)(k0 + wr) * DMODEL + n0 + wc);
        As[ac + 0][ar] = av.x;
        As[ac + 1][ar] = av.y;
        As[ac + 2][ar] = av.z;
        As[ac + 3][ar] = av.w;
        *(float4*)&Ws[wr][wc] = wv;
        __syncthreads();
#pragma unroll
        for (int kk = 0; kk < 8; kk++) {
            float a[8], b[8];
            *(float4*)(a)     = *(float4*)&As[kk][ty * 8];
            *(float4*)(a + 4) = *(float4*)&As[kk][ty * 8 + 4];
            *(float4*)(b)     = *(float4*)&Ws[kk][tx * 8];
            *(float4*)(b + 4) = *(float4*)&Ws[kk][tx * 8 + 4];
#pragma unroll
            for (int i = 0; i < 8; i++)
#pragma unroll
                for (int j = 0; j < 8; j++) acc[i][j] += a[i] * b[j];
        }
        __syncthreads();
    }

#pragma unroll
    for (int i = 0; i < 8; i++) {
        const int row = m0 + ty * 8 + i;
        float* crow = C + (size_t)row * DMODEL + n0 + tx * 8;
#pragma unroll
        for (int j = 0; j < 8; j += 4) {
            float4 o;
            o.x = acc[i][j + 0] + bias[n0 + tx * 8 + j + 0];
            o.y = acc[i][j + 1] + bias[n0 + tx * 8 + j + 1];
            o.z = acc[i][j + 2] + bias[n0 + tx * 8 + j + 2];
            o.w = acc[i][j + 3] + bias[n0 + tx * 8 + j + 3];
            *(float4*)(crow + j) = o;
        }
    }
}

// ---------------- RMSNorm (per head) + RoPE, in-place ----------------------
// One warp handles one (row, head). Rows < split use txt weights/freqs at
// pos=row; rows >= split use img weights/freqs at pos=row-split.
__global__ void normrope_kernel(
    float* __restrict__ X, int rows,
    const float* __restrict__ w_txt, const float* __restrict__ w_img,
    const float* __restrict__ tcos, const float* __restrict__ tsin,
    const float* __restrict__ icos, const float* __restrict__ isin,
    float outscale)
{
    const int id   = blockIdx.x * blockDim.y + threadIdx.y;
    const int lane = threadIdx.x;
    if (id >= rows * NHEAD) return;
    const int row = id / NHEAD;
    const int h   = id % NHEAD;

    float2* p2 = (float2*)(X + (size_t)row * DMODEL + h * HD);
    float2 v0 = p2[lane];
    float2 v1 = p2[lane + 32];

    float ss = v0.x * v0.x + v0.y * v0.y + v1.x * v1.x + v1.y * v1.y;
#pragma unroll
    for (int o = 16; o > 0; o >>= 1) ss += __shfl_xor_sync(0xffffffffu, ss, o);
    const float rms = rsqrtf(ss * (1.0f / 128.0f) + 1e-6f);

    const float *w, *cT, *sT;
    if (row < STXT) { w = w_txt; cT = tcos + (size_t)row * 64;          sT = tsin + (size_t)row * 64; }
    else            { w = w_img; cT = icos + (size_t)(row - STXT) * 64; sT = isin + (size_t)(row - STXT) * 64; }

    {
        int p = lane;
        float c = cT[p], s = sT[p];
        float yr = v0.x * rms * w[2 * p];
        float yi = v0.y * rms * w[2 * p + 1];
        float2 o;
        o.x = (yr * c - yi * s) * outscale;
        o.y = (yr * s + yi * c) * outscale;
        p2[p] = o;
    }
    {
        int p = lane + 32;
        float c = cT[p], s = sT[p];
        float yr = v1.x * rms * w[2 * p];
        float yi = v1.y * rms * w[2 * p + 1];
        float2 o;
        o.x = (yr * c - yi * s) * outscale;
        o.y = (yr * s + yi * c) * outscale;
        p2[p] = o;
    }
}

// ---------------- Flash attention (fp32) ------------------------------------
// grid (LQ/64, NHEAD), 256 threads. 64q x 64kv tiles, online softmax.
// Q is pre-scaled by 1/sqrt(HD). Mask applies to kv columns < STXT.
#define ATTN_SMEM_FLOATS (64*129 + 64*129 + 64*132 + 64*68)
__global__ __launch_bounds__(256) void attn_kernel(
    const float* __restrict__ Q, const float* __restrict__ K,
    const float* __restrict__ V, const int* __restrict__ mask,
    float* __restrict__ O)
{
    extern __shared__ float sm[];
    float* Qs = sm;                    // stride 129
    float* Ks = Qs + 64 * 129;         // stride 129
    float* Vs = Ks + 64 * 129;         // stride 132 (float4-aligned)
    float* Ss = Vs + 64 * 132;         // stride 68

    const int t   = threadIdx.x;
    const int h   = blockIdx.y;
    const int q0g = blockIdx.x * 64;

    // load Q tile (scaled already)
#pragma unroll
    for (int i = 0; i < 8; i++) {
        int idx = t + 256 * i;
        int r = idx >> 5, c4 = (idx & 31) * 4;
        float4 v = *(const float4*)(Q + (size_t)(q0g + r) * DMODEL + h * HD + c4);
        float* dst = Qs + r * 129 + c4;
        dst[0] = v.x; dst[1] = v.y; dst[2] = v.z; dst[3] = v.w;
    }

    const int g  = t >> 4;       // 0..15 -> q group of 4 (phase 1)
    const int e  = t & 15;       // 0..15 -> k group of 4 (phase 1)
    const int qa = t >> 2;       // 0..63 -> query (phase 2)
    const int lq = t & 3;        // quad lane
    const int dbase = lq * 32;   // 32 contiguous dims owned

    float m = -INFINITY, l = 0.f;
    float acc[32];
#pragma unroll
    for (int i = 0; i < 32; i++) acc[i] = 0.f;

    for (int kt = 0; kt < SKV / 64; kt++) {
        const int kb = kt * 64;
        // load K and V tiles
#pragma unroll
        for (int i = 0; i < 8; i++) {
            int idx = t + 256 * i;
            int r = idx >> 5, c4 = (idx & 31) * 4;
            float4 kv = *(const float4*)(K + (size_t)(kb + r) * DMODEL + h * HD + c4);
            float* kd = Ks + r * 129 + c4;
            kd[0] = kv.x; kd[1] = kv.y; kd[2] = kv.z; kd[3] = kv.w;
            float4 vv = *(const float4*)(V + (size_t)(kb + r) * DMODEL + h * HD + c4);
            *(float4*)(Vs + r * 132 + c4) = vv;
        }
        __syncthreads();

        // ---- phase 1: 4x4 scores per thread ----
        float s[4][4];
#pragma unroll
        for (int i = 0; i < 4; i++)
#pragma unroll
            for (int j = 0; j < 4; j++) s[i][j] = 0.f;

        const float* qr0 = Qs + (4 * g + 0) * 129;
        const float* qr1 = Qs + (4 * g + 1) * 129;
        const float* qr2 = Qs + (4 * g + 2) * 129;
        const float* qr3 = Qs + (4 * g + 3) * 129;
        const float* kr0 = Ks + (4 * e + 0) * 129;
        const float* kr1 = Ks + (4 * e + 1) * 129;
        const float* kr2 = Ks + (4 * e + 2) * 129;
        const float* kr3 = Ks + (4 * e + 3) * 129;
#pragma unroll 8
        for (int d = 0; d < 128; d++) {
            float a0 = qr0[d], a1 = qr1[d], a2 = qr2[d], a3 = qr3[d];
            float b0 = kr0[d], b1 = kr1[d], b2 = kr2[d], b3 = kr3[d];
            s[0][0] += a0 * b0; s[0][1] += a0 * b1; s[0][2] += a0 * b2; s[0][3] += a0 * b3;
            s[1][0] += a1 * b0; s[1][1] += a1 * b1; s[1][2] += a1 * b2; s[1][3] += a1 * b3;
            s[2][0] += a2 * b0; s[2][1] += a2 * b1; s[2][2] += a2 * b2; s[2][3] += a2 * b3;
            s[3][0] += a3 * b0; s[3][1] += a3 * b1; s[3][2] += a3 * b2; s[3][3] += a3 * b3;
        }
#pragma unroll
        for (int i = 0; i < 4; i++)
#pragma unroll
            for (int j = 0; j < 4; j++) {
                float sc = s[i][j];
                int kglob = kb + 4 * e + j;
                if (kglob < STXT && mask[kglob] == 0) sc = -1e30f;
                Ss[(4 * g + i) * 68 + 4 * e + j] = sc;
            }
        __syncthreads();

        // ---- phase 2: online softmax per query (quad-cooperative) ----
        float sv[16];
        float tm = -1e30f;
#pragma unroll
        for (int j = 0; j < 16; j++) {
            sv[j] = Ss[qa * 68 + lq + 4 * j];
            tm = fmaxf(tm, sv[j]);
        }
        tm = fmaxf(tm, __shfl_xor_sync(0xffffffffu, tm, 1));
        tm = fmaxf(tm, __shfl_xor_sync(0xffffffffu, tm, 2));
        const float mn   = fmaxf(m, tm);
        const float corr = __expf(m - mn);
        l *= corr;
#pragma unroll
        for (int i = 0; i < 32; i++) acc[i] *= corr;
        float ps = 0.f;
#pragma unroll
        for (int j = 0; j < 16; j++) {
            float p = __expf(sv[j] - mn);
            Ss[qa * 68 + lq + 4 * j] = p;
            ps += p;
        }
        ps += __shfl_xor_sync(0xffffffffu, ps, 1);
        ps += __shfl_xor_sync(0xffffffffu, ps, 2);
        l += ps;
        m = mn;
        __syncwarp();

        // ---- PV ----
        const float* srow = Ss + qa * 68;
#pragma unroll 2
        for (int k = 0; k < 64; k++) {
            float p = srow[k];
            const float4* vr = (const float4*)(Vs + k * 132 + dbase);
#pragma unroll
            for (int ii = 0; ii < 8; ii++) {
                float4 vv = vr[ii];
                acc[ii * 4 + 0] += p * vv.x;
                acc[ii * 4 + 1] += p * vv.y;
                acc[ii * 4 + 2] += p * vv.z;
                acc[ii * 4 + 3] += p * vv.w;
            }
        }
        __syncthreads();
    }

    const float inv = 1.0f / l;
    float* optr = O + (size_t)(q0g + qa) * DMODEL + h * HD + dbase;
#pragma unroll
    for (int ii = 0; ii < 8; ii++) {
        float4 o;
        o.x = acc[ii * 4 + 0] * inv;
        o.y = acc[ii * 4 + 1] * inv;
        o.z = acc[ii * 4 + 2] * inv;
        o.w = acc[ii * 4 + 3] * inv;
        *(float4*)(optr + ii * 4) = o;
    }
}

// ---------------- launch -----------------------------------------------------
extern "C" void kernel_launch(void* const* d_in, const int* in_sizes, int n_in,
                              void* d_out, int out_size)
{
    const float* hidden = (const float*)d_in[0];
    const float* enc    = (const float*)d_in[1];
    const int*   mask   = (const int*)  d_in[2];
    const float* ck     = (const float*)d_in[3];
    const float* cv     = (const float*)d_in[4];
    const float* icos   = (const float*)d_in[5];
    const float* isin   = (const float*)d_in[6];
    const float* tcos   = (const float*)d_in[7];
    const float* tsin   = (const float*)d_in[8];
    const float* Wq     = (const float*)d_in[9];
    const float* bq     = (const float*)d_in[10];
    const float* Wk     = (const float*)d_in[11];
    const float* bk     = (const float*)d_in[12];
    const float* Wv     = (const float*)d_in[13];
    const float* bv     = (const float*)d_in[14];
    const float* Wq_add = (const float*)d_in[15];
    const float* bq_add = (const float*)d_in[16];
    const float* Wk_add = (const float*)d_in[17];
    const float* bk_add = (const float*)d_in[18];
    const float* Wv_add = (const float*)d_in[19];
    const float* bv_add = (const float*)d_in[20];
    const float* nqw    = (const float*)d_in[21];
    const float* nkw    = (const float*)d_in[22];
    const float* naqw   = (const float*)d_in[23];
    const float* nakw   = (const float*)d_in[24];
    const float* Wo     = (const float*)d_in[25];
    const float* bo     = (const float*)d_in[26];
    const float* Wo_add = (const float*)d_in[27];
    const float* bo_add = (const float*)d_in[28];
    float* out = (float*)d_out;

    float *Qb, *Kb, *Vb, *Ob;
    cudaGetSymbolAddress((void**)&Qb, g_Q);
    cudaGetSymbolAddress((void**)&Kb, g_K);
    cudaGetSymbolAddress((void**)&Vb, g_V);
    cudaGetSymbolAddress((void**)&Ob, g_O);

    const size_t smem_bytes = (size_t)ATTN_SMEM_FLOATS * sizeof(float);
    cudaFuncSetAttribute(attn_kernel, cudaFuncAttributeMaxDynamicSharedMemorySize,
                         (int)smem_bytes);

    // cached K/V -> tail of K/V buffers (rows 1280..4351)
    cudaMemcpyAsync(Kb + (size_t)1280 * DMODEL, ck,
                    (size_t)3072 * DMODEL * sizeof(float), cudaMemcpyDeviceToDevice);
    cudaMemcpyAsync(Vb + (size_t)1280 * DMODEL, cv,
                    (size_t)3072 * DMODEL * sizeof(float), cudaMemcpyDeviceToDevice);

    // QKV projections (img rows 256..1279, txt rows 0..255)
    sgemm_bias<<<dim3(24, 8), 256>>>(hidden, Wq, bq, Qb + (size_t)256 * DMODEL);
    sgemm_bias<<<dim3(24, 8), 256>>>(hidden, Wk, bk, Kb + (size_t)256 * DMODEL);
    sgemm_bias<<<dim3(24, 8), 256>>>(hidden, Wv, bv, Vb + (size_t)256 * DMODEL);
    sgemm_bias<<<dim3(24, 2), 256>>>(enc, Wq_add, bq_add, Qb);
    sgemm_bias<<<dim3(24, 2), 256>>>(enc, Wk_add, bk_add, Kb);
    sgemm_bias<<<dim3(24, 2), 256>>>(enc, Wv_add, bv_add, Vb);

    // RMSNorm + RoPE (attention scale folded into Q)
    const float qscale = 0.08838834764831845f; // 1/sqrt(128)
    dim3 nb(32, 8);
    {
        int tot = LQ * NHEAD;
        normrope_kernel<<<(tot + 7) / 8, nb>>>(Qb, LQ, naqw, nqw,
                                               tcos, tsin, icos, isin, qscale);
    }
    {
        int tot = SKV * NHEAD;
        normrope_kernel<<<(tot + 7) / 8, nb>>>(Kb, SKV, nakw, nkw,
                                               tcos, tsin, icos, isin, 1.0f);
    }

    // attention
    attn_kernel<<<dim3(LQ / 64, NHEAD), 256, smem_bytes>>>(Qb, Kb, Vb, mask, Ob);

    // output projections: img rows first (out[:1024*D]), then txt
    sgemm_bias<<<dim3(24, 8), 256>>>(Ob + (size_t)256 * DMODEL, Wo, bo, out);
    sgemm_bias<<<dim3(24, 2), 256>>>(Ob, Wo_add, bo_add, out + (size_t)1024 * DMODEL);
}

// round 2
// speedup vs baseline: 2.4347x; 2.4347x over previous
#include <cuda_runtime.h>
#include <math.h>

#define DMODEL 3072
#define NHEAD  24
#define HD     128
#define LQ     1280     // 256 txt + 1024 img queries
#define SKV    4352     // 256 txt + 1024 den + 3072 cached
#define STXT   256

// ---------------- scratch (device globals: allocation-free) ----------------
__device__ float g_Q[(size_t)LQ  * DMODEL];
__device__ float g_K[(size_t)SKV * DMODEL];
__device__ float g_V[(size_t)SKV * DMODEL];
__device__ float g_O[(size_t)LQ  * DMODEL];

// ---------------- cp.async helpers -----------------------------------------
__device__ __forceinline__ void cp_async16(unsigned dst, const void* src) {
    asm volatile("cp.async.cg.shared.global [%0], [%1], 16;" :: "r"(dst), "l"(src));
}
__device__ __forceinline__ void cp_commit() {
    asm volatile("cp.async.commit_group;");
}
template<int N> __device__ __forceinline__ void cp_wait() {
    asm volatile("cp.async.wait_group %0;" :: "n"(N));
}

// ---------------- fused SGEMM: C = A[M x 3072] @ W[3072 x 3072] + bias ------
// 128x128 tile, BK=16, double-buffered cp.async, 256 threads, 8x8 per thread.
// blockIdx.z selects (W, bias, C) set; A shared across z.
struct GemmSet {
    const float *W0, *W1, *W2;
    const float *b0, *b1, *b2;
    float *C0, *C1, *C2;
};

__global__ __launch_bounds__(256, 2) void sgemm_v2(
    const float* __restrict__ A, GemmSet gs)
{
    __shared__ float As[2][128][16];
    __shared__ float Ws[2][16][128];

    const int z = blockIdx.z;
    const float* __restrict__ W    = (z == 0) ? gs.W0 : (z == 1) ? gs.W1 : gs.W2;
    const float* __restrict__ bias = (z == 0) ? gs.b0 : (z == 1) ? gs.b1 : gs.b2;
    float* __restrict__ C          = (z == 0) ? gs.C0 : (z == 1) ? gs.C1 : gs.C2;

    const int t  = threadIdx.x;
    const int tx = t & 15;        // 0..15
    const int ty = t >> 4;        // 0..15
    const int m0 = blockIdx.y * 128;
    const int n0 = blockIdx.x * 128;

    const unsigned sA = (unsigned)__cvta_generic_to_shared(&As[0][0][0]);
    const unsigned sW = (unsigned)__cvta_generic_to_shared(&Ws[0][0][0]);

    float acc[8][8];
#pragma unroll
    for (int i = 0; i < 8; i++)
#pragma unroll
        for (int j = 0; j < 8; j++) acc[i][j] = 0.f;

    // stage copy: As 512 chunks (row=c>>2, off=(c&3)*4), Ws 512 chunks (row=c>>5, off=(c&31)*4)
#define ISSUE_STAGE(st, k0)                                                          \
    {                                                                                \
        _Pragma("unroll")                                                            \
        for (int c = t; c < 512; c += 256) {                                         \
            int row = c >> 2, off = (c & 3) * 4;                                     \
            cp_async16(sA + (((st)*128 + row) * 16 + off) * 4,                       \
                       A + (size_t)(m0 + row) * DMODEL + (k0) + off);                \
        }                                                                            \
        _Pragma("unroll")                                                            \
        for (int c = t; c < 512; c += 256) {                                         \
            int row = c >> 5, off = (c & 31) * 4;                                    \
            cp_async16(sW + (((st)*16 + row) * 128 + off) * 4,                       \
                       W + (size_t)((k0) + row) * DMODEL + n0 + off);                \
        }                                                                            \
        cp_commit();                                                                 \
    }

    const int NS = DMODEL / 16;   // 192 stages
    ISSUE_STAGE(0, 0)

    for (int s = 0; s < NS; s++) {
        if (s + 1 < NS) {
            ISSUE_STAGE((s + 1) & 1, (s + 1) * 16)
            cp_wait<1>();
        } else {
            cp_wait<0>();
        }
        __syncthreads();
        const int st = s & 1;
#pragma unroll
        for (int kk = 0; kk < 16; kk++) {
            float a[8], b[8];
#pragma unroll
            for (int i = 0; i < 8; i++) a[i] = As[st][ty * 8 + i][kk];
            *(float4*)(b)     = *(const float4*)&Ws[st][kk][tx * 4];
            *(float4*)(b + 4) = *(const float4*)&Ws[st][kk][64 + tx * 4];
#pragma unroll
            for (int i = 0; i < 8; i++)
#pragma unroll
                for (int j = 0; j < 8; j++) acc[i][j] += a[i] * b[j];
        }
        __syncthreads();
    }
#undef ISSUE_STAGE

    // epilogue: columns {n0+4tx..+3} and {n0+64+4tx..+3}
    float4 bA, bB;
    bA.x = bias[n0 + 4 * tx + 0]; bA.y = bias[n0 + 4 * tx + 1];
    bA.z = bias[n0 + 4 * tx + 2]; bA.w = bias[n0 + 4 * tx + 3];
    bB.x = bias[n0 + 64 + 4 * tx + 0]; bB.y = bias[n0 + 64 + 4 * tx + 1];
    bB.z = bias[n0 + 64 + 4 * tx + 2]; bB.w = bias[n0 + 64 + 4 * tx + 3];
#pragma unroll
    for (int i = 0; i < 8; i++) {
        const int row = m0 + ty * 8 + i;
        float* crow = C + (size_t)row * DMODEL + n0;
        float4 o1, o2;
        o1.x = acc[i][0] + bA.x; o1.y = acc[i][1] + bA.y;
        o1.z = acc[i][2] + bA.z; o1.w = acc[i][3] + bA.w;
        o2.x = acc[i][4] + bB.x; o2.y = acc[i][5] + bB.y;
        o2.z = acc[i][6] + bB.z; o2.w = acc[i][7] + bB.w;
        *(float4*)(crow + 4 * tx)      = o1;
        *(float4*)(crow + 64 + 4 * tx) = o2;
    }
}

// ---------------- RMSNorm (per head) + RoPE, in-place ----------------------
__global__ void normrope_kernel(
    float* __restrict__ X, int rows,
    const float* __restrict__ w_txt, const float* __restrict__ w_img,
    const float* __restrict__ tcos, const float* __restrict__ tsin,
    const float* __restrict__ icos, const float* __restrict__ isin,
    float outscale)
{
    const int id   = blockIdx.x * blockDim.y + threadIdx.y;
    const int lane = threadIdx.x;
    if (id >= rows * NHEAD) return;
    const int row = id / NHEAD;
    const int h   = id % NHEAD;

    float2* p2 = (float2*)(X + (size_t)row * DMODEL + h * HD);
    float2 v0 = p2[lane];
    float2 v1 = p2[lane + 32];

    float ss = v0.x * v0.x + v0.y * v0.y + v1.x * v1.x + v1.y * v1.y;
#pragma unroll
    for (int o = 16; o > 0; o >>= 1) ss += __shfl_xor_sync(0xffffffffu, ss, o);
    const float rms = rsqrtf(ss * (1.0f / 128.0f) + 1e-6f);

    const float *w, *cT, *sT;
    if (row < STXT) { w = w_txt; cT = tcos + (size_t)row * 64;          sT = tsin + (size_t)row * 64; }
    else            { w = w_img; cT = icos + (size_t)(row - STXT) * 64; sT = isin + (size_t)(row - STXT) * 64; }

    {
        int p = lane;
        float c = cT[p], s = sT[p];
        float yr = v0.x * rms * w[2 * p];
        float yi = v0.y * rms * w[2 * p + 1];
        float2 o;
        o.x = (yr * c - yi * s) * outscale;
        o.y = (yr * s + yi * c) * outscale;
        p2[p] = o;
    }
    {
        int p = lane + 32;
        float c = cT[p], s = sT[p];
        float yr = v1.x * rms * w[2 * p];
        float yi = v1.y * rms * w[2 * p + 1];
        float2 o;
        o.x = (yr * c - yi * s) * outscale;
        o.y = (yr * s + yi * c) * outscale;
        p2[p] = o;
    }
}

// ---------------- Flash attention (fp32, cp.async double-buffered) ----------
// grid (LQ/64, NHEAD), 256 threads. 64q x 64kv tiles, online softmax.
#define QK_STRIDE 132
#define KV_TILE   (64 * QK_STRIDE)
#define SS_STRIDE 68
#define ATTN_SMEM_FLOATS (KV_TILE /*Q*/ + 2 * KV_TILE /*K*/ + 2 * KV_TILE /*V*/ + 64 * SS_STRIDE)

__global__ __launch_bounds__(256) void attn_kernel(
    const float* __restrict__ Q, const float* __restrict__ K,
    const float* __restrict__ V, const int* __restrict__ mask,
    float* __restrict__ O)
{
    extern __shared__ float sm[];
    float* Qs = sm;                                // [64][132]
    float* Ks = Qs + KV_TILE;                      // [2][64][132]
    float* Vs = Ks + 2 * KV_TILE;                  // [2][64][132]
    float* Ss = Vs + 2 * KV_TILE;                  // [64][68]

    const unsigned sK = (unsigned)__cvta_generic_to_shared(Ks);
    const unsigned sV = (unsigned)__cvta_generic_to_shared(Vs);

    const int t   = threadIdx.x;
    const int h   = blockIdx.y;
    const int q0g = blockIdx.x * 64;

    // load Q tile (pre-scaled)
#pragma unroll
    for (int i = 0; i < 8; i++) {
        int idx = t + 256 * i;
        int r = idx >> 5, c4 = (idx & 31) * 4;
        float4 v = *(const float4*)(Q + (size_t)(q0g + r) * DMODEL + h * HD + c4);
        *(float4*)(Qs + r * QK_STRIDE + c4) = v;
    }

    const int g  = t >> 4;       // q base row (phase 1): rows g + 16i
    const int e  = t & 15;       // k base col (phase 1): cols e + 16j
    const int qa = t >> 2;       // query (phase 2 / PV)
    const int lq = t & 3;        // quad lane; owns d cols {16*ii + 4*lq + 0..3}

    float m = -INFINITY, l = 0.f;
    float acc[32];
#pragma unroll
    for (int i = 0; i < 32; i++) acc[i] = 0.f;

    // K/V stage copy: 2048 chunks each, row = c>>5, off = (c&31)*4
#define ISSUE_KV(st, kb)                                                              \
    {                                                                                 \
        _Pragma("unroll")                                                             \
        for (int c = t; c < 2048; c += 256) {                                         \
            int row = c >> 5, off = (c & 31) * 4;                                     \
            const size_t gofs = (size_t)((kb) + row) * DMODEL + h * HD + off;         \
            unsigned d = (unsigned)(((st) * KV_TILE + row * QK_STRIDE + off) * 4);    \
            cp_async16(sK + d, K + gofs);                                             \
            cp_async16(sV + d, V + gofs);                                             \
        }                                                                             \
        cp_commit();                                                                  \
    }

    const int NT = SKV / 64;   // 68 tiles
    ISSUE_KV(0, 0)

    for (int kt = 0; kt < NT; kt++) {
        const int kb = kt * 64;
        if (kt + 1 < NT) {
            ISSUE_KV((kt + 1) & 1, (kt + 1) * 64)
            cp_wait<1>();
        } else {
            cp_wait<0>();
        }
        __syncthreads();
        const float* Kt = Ks + (kt & 1) * KV_TILE;
        const float* Vt = Vs + (kt & 1) * KV_TILE;

        // ---- phase 1: dispersed 4x4 scores, float4 over d ----
        float s[4][4];
#pragma unroll
        for (int i = 0; i < 4; i++)
#pragma unroll
            for (int j = 0; j < 4; j++) s[i][j] = 0.f;

#pragma unroll 4
        for (int d4 = 0; d4 < 128; d4 += 4) {
            float4 a0 = *(const float4*)(Qs + (g +  0) * QK_STRIDE + d4);
            float4 a1 = *(const float4*)(Qs + (g + 16) * QK_STRIDE + d4);
            float4 a2 = *(const float4*)(Qs + (g + 32) * QK_STRIDE + d4);
            float4 a3 = *(const float4*)(Qs + (g + 48) * QK_STRIDE + d4);
            float4 b0 = *(const float4*)(Kt + (e +  0) * QK_STRIDE + d4);
            float4 b1 = *(const float4*)(Kt + (e + 16) * QK_STRIDE + d4);
            float4 b2 = *(const float4*)(Kt + (e + 32) * QK_STRIDE + d4);
            float4 b3 = *(const float4*)(Kt + (e + 48) * QK_STRIDE + d4);
#define QKDOT(i, av)                                                     \
            s[i][0] += av.x * b0.x + av.y * b0.y + av.z * b0.z + av.w * b0.w; \
            s[i][1] += av.x * b1.x + av.y * b1.y + av.z * b1.z + av.w * b1.w; \
            s[i][2] += av.x * b2.x + av.y * b2.y + av.z * b2.z + av.w * b2.w; \
            s[i][3] += av.x * b3.x + av.y * b3.y + av.z * b3.z + av.w * b3.w;
            QKDOT(0, a0) QKDOT(1, a1) QKDOT(2, a2) QKDOT(3, a3)
#undef QKDOT
        }
#pragma unroll
        for (int i = 0; i < 4; i++)
#pragma unroll
            for (int j = 0; j < 4; j++) {
                float sc = s[i][j];
                int kglob = kb + e + 16 * j;
                if (kglob < STXT && mask[kglob] == 0) sc = -1e30f;
                Ss[(g + 16 * i) * SS_STRIDE + e + 16 * j] = sc;
            }
        __syncthreads();

        // ---- phase 2: online softmax per query (quad-cooperative) ----
        float sv[16];
        float tm = -1e30f;
#pragma unroll
        for (int j = 0; j < 16; j++) {
            sv[j] = Ss[qa * SS_STRIDE + lq + 4 * j];
            tm = fmaxf(tm, sv[j]);
        }
        tm = fmaxf(tm, __shfl_xor_sync(0xffffffffu, tm, 1));
        tm = fmaxf(tm, __shfl_xor_sync(0xffffffffu, tm, 2));
        const float mn   = fmaxf(m, tm);
        const float corr = __expf(m - mn);
        l *= corr;
#pragma unroll
        for (int i = 0; i < 32; i++) acc[i] *= corr;
        float ps = 0.f;
#pragma unroll
        for (int j = 0; j < 16; j++) {
            float p = __expf(sv[j] - mn);
            Ss[qa * SS_STRIDE + lq + 4 * j] = p;
            ps += p;
        }
        ps += __shfl_xor_sync(0xffffffffu, ps, 1);
        ps += __shfl_xor_sync(0xffffffffu, ps, 2);
        l += ps;
        m = mn;
        __syncwarp();

        // ---- PV: thread owns d cols {16*ii + 4*lq} ----
        const float* srow = Ss + qa * SS_STRIDE;
#pragma unroll 2
        for (int k = 0; k < 64; k++) {
            float p = srow[k];
            const float* vr = Vt + k * QK_STRIDE + 4 * lq;
#pragma unroll
            for (int ii = 0; ii < 8; ii++) {
                float4 vv = *(const float4*)(vr + 16 * ii);
                acc[ii * 4 + 0] += p * vv.x;
                acc[ii * 4 + 1] += p * vv.y;
                acc[ii * 4 + 2] += p * vv.z;
                acc[ii * 4 + 3] += p * vv.w;
            }
        }
        __syncthreads();
    }
#undef ISSUE_KV

    const float inv = 1.0f / l;
    float* optr = O + (size_t)(q0g + qa) * DMODEL + h * HD + 4 * lq;
#pragma unroll
    for (int ii = 0; ii < 8; ii++) {
        float4 o;
        o.x = acc[ii * 4 + 0] * inv;
        o.y = acc[ii * 4 + 1] * inv;
        o.z = acc[ii * 4 + 2] * inv;
        o.w = acc[ii * 4 + 3] * inv;
        *(float4*)(optr + 16 * ii) = o;
    }
}

// ---------------- launch -----------------------------------------------------
extern "C" void kernel_launch(void* const* d_in, const int* in_sizes, int n_in,
                              void* d_out, int out_size)
{
    const float* hidden = (const float*)d_in[0];
    const float* enc    = (const float*)d_in[1];
    const int*   mask   = (const int*)  d_in[2];
    const float* ck     = (const float*)d_in[3];
    const float* cv     = (const float*)d_in[4];
    const float* icos   = (const float*)d_in[5];
    const float* isin   = (const float*)d_in[6];
    const float* tcos   = (const float*)d_in[7];
    const float* tsin   = (const float*)d_in[8];
    const float* Wq     = (const float*)d_in[9];
    const float* bq     = (const float*)d_in[10];
    const float* Wk     = (const float*)d_in[11];
    const float* bk     = (const float*)d_in[12];
    const float* Wv     = (const float*)d_in[13];
    const float* bv     = (const float*)d_in[14];
    const float* Wq_add = (const float*)d_in[15];
    const float* bq_add = (const float*)d_in[16];
    const float* Wk_add = (const float*)d_in[17];
    const float* bk_add = (const float*)d_in[18];
    const float* Wv_add = (const float*)d_in[19];
    const float* bv_add = (const float*)d_in[20];
    const float* nqw    = (const float*)d_in[21];
    const float* nkw    = (const float*)d_in[22];
    const float* naqw   = (const float*)d_in[23];
    const float* nakw   = (const float*)d_in[24];
    const float* Wo     = (const float*)d_in[25];
    const float* bo     = (const float*)d_in[26];
    const float* Wo_add = (const float*)d_in[27];
    const float* bo_add = (const float*)d_in[28];
    float* out = (float*)d_out;

    float *Qb, *Kb, *Vb, *Ob;
    cudaGetSymbolAddress((void**)&Qb, g_Q);
    cudaGetSymbolAddress((void**)&Kb, g_K);
    cudaGetSymbolAddress((void**)&Vb, g_V);
    cudaGetSymbolAddress((void**)&Ob, g_O);

    const size_t smem_bytes = (size_t)ATTN_SMEM_FLOATS * sizeof(float);
    cudaFuncSetAttribute(attn_kernel, cudaFuncAttributeMaxDynamicSharedMemorySize,
                         (int)smem_bytes);

    // cached K/V -> tail of K/V buffers (rows 1280..4351)
    cudaMemcpyAsync(Kb + (size_t)1280 * DMODEL, ck,
                    (size_t)3072 * DMODEL * sizeof(float), cudaMemcpyDeviceToDevice);
    cudaMemcpyAsync(Vb + (size_t)1280 * DMODEL, cv,
                    (size_t)3072 * DMODEL * sizeof(float), cudaMemcpyDeviceToDevice);

    // QKV projections, fused across z (img rows 256..1279, txt rows 0..255)
    {
        GemmSet gi = { Wq, Wk, Wv, bq, bk, bv,
                       Qb + (size_t)256 * DMODEL, Kb + (size_t)256 * DMODEL,
                       Vb + (size_t)256 * DMODEL };
        sgemm_v2<<<dim3(24, 8, 3), 256>>>(hidden, gi);
        GemmSet gt = { Wq_add, Wk_add, Wv_add, bq_add, bk_add, bv_add,
                       Qb, Kb, Vb };
        sgemm_v2<<<dim3(24, 2, 3), 256>>>(enc, gt);
    }

    // RMSNorm + RoPE (attention scale folded into Q)
    const float qscale = 0.08838834764831845f; // 1/sqrt(128)
    dim3 nb(32, 8);
    {
        int tot = LQ * NHEAD;
        normrope_kernel<<<(tot + 7) / 8, nb>>>(Qb, LQ, naqw, nqw,
                                               tcos, tsin, icos, isin, qscale);
    }
    {
        int tot = SKV * NHEAD;
        normrope_kernel<<<(tot + 7) / 8, nb>>>(Kb, SKV, nakw, nkw,
                                               tcos, tsin, icos, isin, 1.0f);
    }

    // attention
    attn_kernel<<<dim3(LQ / 64, NHEAD), 256, smem_bytes>>>(Qb, Kb, Vb, mask, Ob);

    // output projections: img rows -> out[:1024*D], txt rows -> out[1024*D:]
    {
        GemmSet go = { Wo, Wo, Wo, bo, bo, bo, out, out, out };
        sgemm_v2<<<dim3(24, 8, 1), 256>>>(Ob + (size_t)256 * DMODEL, go);
        GemmSet ga = { Wo_add, Wo_add, Wo_add, bo_add, bo_add, bo_add,
                       out + (size_t)1024 * DMODEL,
                       out + (size_t)1024 * DMODEL,
                       out + (size_t)1024 * DMODEL };
        sgemm_v2<<<dim3(24, 2, 1), 256>>>(Ob, ga);
    }
}

// round 4
// speedup vs baseline: 3.0565x; 1.2554x over previous
#include <cuda_runtime.h>
#include <cuda_bf16.h>
#include <math.h>
#include <stdint.h>

#define DMODEL 3072
#define NHEAD  24
#define HD     128
#define LQ     1280     // 256 txt + 1024 img queries
#define SKV    4352     // 256 txt + 1024 den + 3072 cached
#define STXT   256

// ---------------- scratch (device globals: allocation-free) ----------------
__device__ float g_Q[(size_t)LQ  * DMODEL];
__device__ float g_K[(size_t)SKV * DMODEL];
__device__ float g_V[(size_t)SKV * DMODEL];
__device__ float g_O[(size_t)LQ  * DMODEL];

// bf16 hi/lo split buffers
#define WELEMS ((size_t)DMODEL * DMODEL)
__device__ __nv_bfloat16 g_WhT[8 * WELEMS];   // transposed [N][K], hi
__device__ __nv_bfloat16 g_WlT[8 * WELEMS];   // transposed [N][K], lo
__device__ __nv_bfloat16 g_Ah[(size_t)LQ * DMODEL];
__device__ __nv_bfloat16 g_Al[(size_t)LQ * DMODEL];
__device__ __nv_bfloat16 g_Eh[(size_t)STXT * DMODEL];
__device__ __nv_bfloat16 g_El[(size_t)STXT * DMODEL];

// ---------------- PTX helpers -----------------------------------------------
__device__ __forceinline__ void cp_async16(unsigned dst, const void* src) {
    asm volatile("cp.async.cg.shared.global [%0], [%1], 16;" :: "r"(dst), "l"(src));
}
__device__ __forceinline__ void cp_commit() {
    asm volatile("cp.async.commit_group;");
}
template<int N> __device__ __forceinline__ void cp_wait() {
    asm volatile("cp.async.wait_group %0;" :: "n"(N));
}
__device__ __forceinline__ uint32_t smem_u32(const void* p) {
    uint32_t a;
    asm("{ .reg .u64 t; cvta.to.shared.u64 t, %1; cvt.u32.u64 %0, t; }" : "=r"(a) : "l"(p));
    return a;
}

#define LDSM_X4(r0, r1, r2, r3, addr)                                           \
    asm volatile("ldmatrix.sync.aligned.m8n8.x4.shared.b16 {%0,%1,%2,%3}, [%4];" \
        : "=r"(r0), "=r"(r1), "=r"(r2), "=r"(r3) : "r"(addr))

#define MMA16816(d, a0, a1, a2, a3, b0, b1)                                     \
    asm volatile("mma.sync.aligned.m16n8k16.row.col.f32.bf16.bf16.f32 "         \
        "{%0,%1,%2,%3},{%4,%5,%6,%7},{%8,%9},{%0,%1,%2,%3};"                    \
        : "+f"((d)[0]), "+f"((d)[1]), "+f"((d)[2]), "+f"((d)[3])                \
        : "r"(a0), "r"(a1), "r"(a2), "r"(a3), "r"(b0), "r"(b1))

// ---------------- conversion kernels ----------------------------------------
// split fp32 -> (hi, lo) bf16, same layout
__global__ void convert_hl(const float4* __restrict__ X,
                           __nv_bfloat162* __restrict__ H,
                           __nv_bfloat162* __restrict__ L, int n4)
{
    int i = blockIdx.x * 256 + threadIdx.x;
    if (i >= n4) return;
    float4 v = X[i];
    __nv_bfloat16 h0 = __float2bfloat16(v.x);
    __nv_bfloat16 h1 = __float2bfloat16(v.y);
    __nv_bfloat16 h2 = __float2bfloat16(v.z);
    __nv_bfloat16 h3 = __float2bfloat16(v.w);
    __nv_bfloat16 l0 = __float2bfloat16(v.x - __bfloat162float(h0));
    __nv_bfloat16 l1 = __float2bfloat16(v.y - __bfloat162float(h1));
    __nv_bfloat16 l2 = __float2bfloat16(v.z - __bfloat162float(h2));
    __nv_bfloat16 l3 = __float2bfloat16(v.w - __bfloat162float(h3));
    H[2 * i]     = __nv_bfloat162(h0, h1);
    H[2 * i + 1] = __nv_bfloat162(h2, h3);
    L[2 * i]     = __nv_bfloat162(l0, l1);
    L[2 * i + 1] = __nv_bfloat162(l2, l3);
}

// split + transpose 8 weight matrices: W[K][N] fp32 -> WhT/WlT[N][K] bf16
struct WSrc { const float* p[8]; };

__global__ void convert_hl_T(WSrc ws, __nv_bfloat16* __restrict__ Ht,
                             __nv_bfloat16* __restrict__ Lt)
{
    __shared__ float tile[32][33];
    const int mtx = blockIdx.z;
    const float* __restrict__ W = ws.p[mtx];
    const size_t base = (size_t)mtx * WELEMS;
    const int tx = threadIdx.x;           // 0..31
    const int ty = threadIdx.y;           // 0..7
    const int n0 = blockIdx.x * 32;
    const int k0 = blockIdx.y * 32;
#pragma unroll
    for (int i = 0; i < 4; i++)
        tile[ty + 8 * i][tx] = W[(size_t)(k0 + ty + 8 * i) * DMODEL + n0 + tx];
    __syncthreads();
#pragma unroll
    for (int i = 0; i < 4; i++) {
        float x = tile[tx][ty + 8 * i];
        __nv_bfloat16 h = __float2bfloat16(x);
        __nv_bfloat16 l = __float2bfloat16(x - __bfloat162float(h));
        size_t ofs = base + (size_t)(n0 + ty + 8 * i) * DMODEL + k0 + tx;
        Ht[ofs] = h;
        Lt[ofs] = l;
    }
}

// ---------------- mma.sync bf16 hi/lo GEMM -----------------------------------
// C[M x 3072] = A[M x 3072] @ W[3072 x 3072] + bias.
// CTA 128x128, BK=32, 8 warps (2x4), warp tile 64x32 of m16n8k16.
struct TGemmSet {
    const __nv_bfloat16 *wh[3], *wl[3];
    const float* b[3];
    float* c[3];
};

// stage layout (bf16 elems): Ah[128][40] | Al | Bh[128][40] | Bl
#define SUB_ELEMS   (128 * 40)
#define STAGE_ELEMS (4 * SUB_ELEMS)
#define STAGE_BYTES (STAGE_ELEMS * 2)       // 40960
#define MG_SMEM     (2 * STAGE_BYTES)       // 81920

__device__ __forceinline__ void mg_load_stage(
    uint32_t sb, int stage,
    const __nv_bfloat16* __restrict__ Ah, const __nv_bfloat16* __restrict__ Al,
    const __nv_bfloat16* __restrict__ Wh, const __nv_bfloat16* __restrict__ Wl,
    int m0, int n0, int k0, int t)
{
    const uint32_t s0 = sb + stage * STAGE_BYTES;
#pragma unroll
    for (int c = t; c < 512; c += 256) {
        const int row = c >> 2;
        const int ch  = (c & 3) * 8;                      // elem offset in row
        const uint32_t d = s0 + (row * 40 + ch) * 2;
        const size_t ga = (size_t)(m0 + row) * DMODEL + k0 + ch;
        const size_t gb = (size_t)(n0 + row) * DMODEL + k0 + ch;
        cp_async16(d,                     Ah + ga);
        cp_async16(d + 1 * SUB_ELEMS * 2, Al + ga);
        cp_async16(d + 2 * SUB_ELEMS * 2, Wh + gb);
        cp_async16(d + 3 * SUB_ELEMS * 2, Wl + gb);
    }
    cp_commit();
}

__global__ __launch_bounds__(256) void mma_gemm(
    const __nv_bfloat16* __restrict__ Ah,
    const __nv_bfloat16* __restrict__ Al, TGemmSet gs)
{
    extern __shared__ __align__(128) __nv_bfloat16 smg[];
    const uint32_t sb = smem_u32(smg);

    const int z = blockIdx.z;
    const __nv_bfloat16* __restrict__ Wh = gs.wh[z];
    const __nv_bfloat16* __restrict__ Wl = gs.wl[z];
    const float* __restrict__ bias = gs.b[z];
    float* __restrict__ C = gs.c[z];

    const int t    = threadIdx.x;
    const int wid  = t >> 5;
    const int lane = t & 31;
    const int wm   = wid >> 2;        // 0..1
    const int wn   = wid & 3;         // 0..3
    const int m0   = blockIdx.y * 128;
    const int n0   = blockIdx.x * 128;

    // ldmatrix per-lane element offsets (col k-offset added later)
    const int mat = lane >> 3, r = lane & 7;
    int aOff[4], bOff[2];
#pragma unroll
    for (int i = 0; i < 4; i++)
        aOff[i] = (wm * 64 + 16 * i + (mat & 1) * 8 + r) * 40 + (mat >> 1) * 8;
#pragma unroll
    for (int p = 0; p < 2; p++)
        bOff[p] = (wn * 32 + 16 * p + (mat >> 1) * 8 + r) * 40 + (mat & 1) * 8;

    float acc[4][4][4];
#pragma unroll
    for (int i = 0; i < 4; i++)
#pragma unroll
        for (int j = 0; j < 4; j++)
#pragma unroll
            for (int q = 0; q < 4; q++) acc[i][j][q] = 0.f;

    const int NS = DMODEL / 32;   // 96
    mg_load_stage(sb, 0, Ah, Al, Wh, Wl, m0, n0, 0,  t);
    mg_load_stage(sb, 1, Ah, Al, Wh, Wl, m0, n0, 32, t);

    for (int s = 0; s < NS; s++) {
        if (s + 1 < NS) cp_wait<1>(); else cp_wait<0>();
        __syncthreads();
        const uint32_t s0 = sb + (s & 1) * STAGE_BYTES;

#pragma unroll
        for (int ks = 0; ks < 2; ks++) {
            const int ke = ks * 16;
            uint32_t ah[4][4], al[4][4], bh[2][4], bl[2][4];
#pragma unroll
            for (int i = 0; i < 4; i++) {
                LDSM_X4(ah[i][0], ah[i][1], ah[i][2], ah[i][3],
                        s0 + (aOff[i] + ke) * 2);
                LDSM_X4(al[i][0], al[i][1], al[i][2], al[i][3],
                        s0 + 1 * SUB_ELEMS * 2 + (aOff[i] + ke) * 2);
            }
#pragma unroll
            for (int p = 0; p < 2; p++) {
                LDSM_X4(bh[p][0], bh[p][1], bh[p][2], bh[p][3],
                        s0 + 2 * SUB_ELEMS * 2 + (bOff[p] + ke) * 2);
                LDSM_X4(bl[p][0], bl[p][1], bl[p][2], bl[p][3],
                        s0 + 3 * SUB_ELEMS * 2 + (bOff[p] + ke) * 2);
            }
#pragma unroll
            for (int i = 0; i < 4; i++)
#pragma unroll
                for (int j = 0; j < 4; j++) {
                    const int p = j >> 1, q = (j & 1) * 2;
                    MMA16816(acc[i][j], ah[i][0], ah[i][1], ah[i][2], ah[i][3],
                             bh[p][q], bh[p][q + 1]);
                    MMA16816(acc[i][j], ah[i][0], ah[i][1], ah[i][2], ah[i][3],
                             bl[p][q], bl[p][q + 1]);
                    MMA16816(acc[i][j], al[i][0], al[i][1], al[i][2], al[i][3],
                             bh[p][q], bh[p][q + 1]);
                }
        }
        __syncthreads();
        if (s + 2 < NS)
            mg_load_stage(sb, s & 1, Ah, Al, Wh, Wl, m0, n0, (s + 2) * 32, t);
    }

    // epilogue: acc[i][j]: rows m0+wm*64+16i+{r4, r4+8}, cols n0+wn*32+8j+c2..+1
    const int r4 = lane >> 2;
    const int c2 = (lane & 3) * 2;
#pragma unroll
    for (int i = 0; i < 4; i++) {
        const int grow = m0 + wm * 64 + 16 * i + r4;
#pragma unroll
        for (int j = 0; j < 4; j++) {
            const int gcol = n0 + wn * 32 + 8 * j + c2;
            const float b0 = bias[gcol], b1 = bias[gcol + 1];
            float2 v0, v1;
            v0.x = acc[i][j][0] + b0; v0.y = acc[i][j][1] + b1;
            v1.x = acc[i][j][2] + b0; v1.y = acc[i][j][3] + b1;
            *(float2*)(C + (size_t)grow * DMODEL + gcol)       = v0;
            *(float2*)(C + (size_t)(grow + 8) * DMODEL + gcol) = v1;
        }
    }
}

// ---------------- RMSNorm (per head) + RoPE, in-place ----------------------
__global__ void normrope_kernel(
    float* __restrict__ X, int rows,
    const float* __restrict__ w_txt, const float* __restrict__ w_img,
    const float* __restrict__ tcos, const float* __restrict__ tsin,
    const float* __restrict__ icos, const float* __restrict__ isin,
    float outscale)
{
    const int id   = blockIdx.x * blockDim.y + threadIdx.y;
    const int lane = threadIdx.x;
    if (id >= rows * NHEAD) return;
    const int row = id / NHEAD;
    const int h   = id % NHEAD;

    float2* p2 = (float2*)(X + (size_t)row * DMODEL + h * HD);
    float2 v0 = p2[lane];
    float2 v1 = p2[lane + 32];

    float ss = v0.x * v0.x + v0.y * v0.y + v1.x * v1.x + v1.y * v1.y;
#pragma unroll
    for (int o = 16; o > 0; o >>= 1) ss += __shfl_xor_sync(0xffffffffu, ss, o);
    const float rms = rsqrtf(ss * (1.0f / 128.0f) + 1e-6f);

    const float *w, *cT, *sT;
    if (row < STXT) { w = w_txt; cT = tcos + (size_t)row * 64;          sT = tsin + (size_t)row * 64; }
    else            { w = w_img; cT = icos + (size_t)(row - STXT) * 64; sT = isin + (size_t)(row - STXT) * 64; }

    {
        int p = lane;
        float c = cT[p], s = sT[p];
        float yr = v0.x * rms * w[2 * p];
        float yi = v0.y * rms * w[2 * p + 1];
        float2 o;
        o.x = (yr * c - yi * s) * outscale;
        o.y = (yr * s + yi * c) * outscale;
        p2[p] = o;
    }
    {
        int p = lane + 32;
        float c = cT[p], s = sT[p];
        float yr = v1.x * rms * w[2 * p];
        float yi = v1.y * rms * w[2 * p + 1];
        float2 o;
        o.x = (yr * c - yi * s) * outscale;
        o.y = (yr * s + yi * c) * outscale;
        p2[p] = o;
    }
}

// ---------------- Flash attention (fp32, cp.async double-buffered) ----------
#define QK_STRIDE 132
#define KV_TILE   (64 * QK_STRIDE)
#define SS_STRIDE 68
#define ATTN_SMEM_FLOATS (KV_TILE + 2 * KV_TILE + 2 * KV_TILE + 64 * SS_STRIDE)

__global__ __launch_bounds__(256) void attn_kernel(
    const float* __restrict__ Q, const float* __restrict__ K,
    const float* __restrict__ V, const int* __restrict__ mask,
    float* __restrict__ O)
{
    extern __shared__ float sm[];
    float* Qs = sm;                                // [64][132]
    float* Ks = Qs + KV_TILE;                      // [2][64][132]
    float* Vs = Ks + 2 * KV_TILE;                  // [2][64][132]
    float* Ss = Vs + 2 * KV_TILE;                  // [64][68]

    const unsigned sK = (unsigned)__cvta_generic_to_shared(Ks);
    const unsigned sV = (unsigned)__cvta_generic_to_shared(Vs);

    const int t   = threadIdx.x;
    const int h   = blockIdx.y;
    const int q0g = blockIdx.x * 64;

#pragma unroll
    for (int i = 0; i < 8; i++) {
        int idx = t + 256 * i;
        int r = idx >> 5, c4 = (idx & 31) * 4;
        float4 v = *(const float4*)(Q + (size_t)(q0g + r) * DMODEL + h * HD + c4);
        *(float4*)(Qs + r * QK_STRIDE + c4) = v;
    }

    const int g  = t >> 4;
    const int e  = t & 15;
    const int qa = t >> 2;
    const int lq = t & 3;

    float m = -INFINITY, l = 0.f;
    float acc[32];
#pragma unroll
    for (int i = 0; i < 32; i++) acc[i] = 0.f;

#define ISSUE_KV(st, kb)                                                              \
    {                                                                                 \
        _Pragma("unroll")                                                             \
        for (int c = t; c < 2048; c += 256) {                                         \
            int row = c >> 5, off = (c & 31) * 4;                                     \
            const size_t gofs = (size_t)((kb) + row) * DMODEL + h * HD + off;         \
            unsigned d = (unsigned)(((st) * KV_TILE + row * QK_STRIDE + off) * 4);    \
            cp_async16(sK + d, K + gofs);                                             \
            cp_async16(sV + d, V + gofs);                                             \
        }                                                                             \
        cp_commit();                                                                  \
    }

    const int NT = SKV / 64;
    ISSUE_KV(0, 0)

    for (int kt = 0; kt < NT; kt++) {
        const int kb = kt * 64;
        if (kt + 1 < NT) {
            ISSUE_KV((kt + 1) & 1, (kt + 1) * 64)
            cp_wait<1>();
        } else {
            cp_wait<0>();
        }
        __syncthreads();
        const float* Kt = Ks + (kt & 1) * KV_TILE;
        const float* Vt = Vs + (kt & 1) * KV_TILE;

        float s[4][4];
#pragma unroll
        for (int i = 0; i < 4; i++)
#pragma unroll
            for (int j = 0; j < 4; j++) s[i][j] = 0.f;

#pragma unroll 4
        for (int d4 = 0; d4 < 128; d4 += 4) {
            float4 a0 = *(const float4*)(Qs + (g +  0) * QK_STRIDE + d4);
            float4 a1 = *(const float4*)(Qs + (g + 16) * QK_STRIDE + d4);
            float4 a2 = *(const float4*)(Qs + (g + 32) * QK_STRIDE + d4);
            float4 a3 = *(const float4*)(Qs + (g + 48) * QK_STRIDE + d4);
            float4 b0 = *(const float4*)(Kt + (e +  0) * QK_STRIDE + d4);
            float4 b1 = *(const float4*)(Kt + (e + 16) * QK_STRIDE + d4);
            float4 b2 = *(const float4*)(Kt + (e + 32) * QK_STRIDE + d4);
            float4 b3 = *(const float4*)(Kt + (e + 48) * QK_STRIDE + d4);
#define QKDOT(i, av)                                                     \
            s[i][0] += av.x * b0.x + av.y * b0.y + av.z * b0.z + av.w * b0.w; \
            s[i][1] += av.x * b1.x + av.y * b1.y + av.z * b1.z + av.w * b1.w; \
            s[i][2] += av.x * b2.x + av.y * b2.y + av.z * b2.z + av.w * b2.w; \
            s[i][3] += av.x * b3.x + av.y * b3.y + av.z * b3.z + av.w * b3.w;
            QKDOT(0, a0) QKDOT(1, a1) QKDOT(2, a2) QKDOT(3, a3)
#undef QKDOT
        }
#pragma unroll
        for (int i = 0; i < 4; i++)
#pragma unroll
            for (int j = 0; j < 4; j++) {
                float sc = s[i][j];
                int kglob = kb + e + 16 * j;
                if (kglob < STXT && mask[kglob] == 0) sc = -1e30f;
                Ss[(g + 16 * i) * SS_STRIDE + e + 16 * j] = sc;
            }
        __syncthreads();

        float sv[16];
        float tm = -1e30f;
#pragma unroll
        for (int j = 0; j < 16; j++) {
            sv[j] = Ss[qa * SS_STRIDE + lq + 4 * j];
            tm = fmaxf(tm, sv[j]);
        }
        tm = fmaxf(tm, __shfl_xor_sync(0xffffffffu, tm, 1));
        tm = fmaxf(tm, __shfl_xor_sync(0xffffffffu, tm, 2));
        const float mn   = fmaxf(m, tm);
        const float corr = __expf(m - mn);
        l *= corr;
#pragma unroll
        for (int i = 0; i < 32; i++) acc[i] *= corr;
        float ps = 0.f;
#pragma unroll
        for (int j = 0; j < 16; j++) {
            float p = __expf(sv[j] - mn);
            Ss[qa * SS_STRIDE + lq + 4 * j] = p;
            ps += p;
        }
        ps += __shfl_xor_sync(0xffffffffu, ps, 1);
        ps += __shfl_xor_sync(0xffffffffu, ps, 2);
        l += ps;
        m = mn;
        __syncwarp();

        const float* srow = Ss + qa * SS_STRIDE;
#pragma unroll 2
        for (int k = 0; k < 64; k++) {
            float p = srow[k];
            const float* vr = Vt + k * QK_STRIDE + 4 * lq;
#pragma unroll
            for (int ii = 0; ii < 8; ii++) {
                float4 vv = *(const float4*)(vr + 16 * ii);
                acc[ii * 4 + 0] += p * vv.x;
                acc[ii * 4 + 1] += p * vv.y;
                acc[ii * 4 + 2] += p * vv.z;
                acc[ii * 4 + 3] += p * vv.w;
            }
        }
        __syncthreads();
    }
#undef ISSUE_KV

    const float inv = 1.0f / l;
    float* optr = O + (size_t)(q0g + qa) * DMODEL + h * HD + 4 * lq;
#pragma unroll
    for (int ii = 0; ii < 8; ii++) {
        float4 o;
        o.x = acc[ii * 4 + 0] * inv;
        o.y = acc[ii * 4 + 1] * inv;
        o.z = acc[ii * 4 + 2] * inv;
        o.w = acc[ii * 4 + 3] * inv;
        *(float4*)(optr + 16 * ii) = o;
    }
}

// ---------------- launch -----------------------------------------------------
extern "C" void kernel_launch(void* const* d_in, const int* in_sizes, int n_in,
                              void* d_out, int out_size)
{
    const float* hidden = (const float*)d_in[0];
    const float* enc    = (const float*)d_in[1];
    const int*   mask   = (const int*)  d_in[2];
    const float* ck     = (const float*)d_in[3];
    const float* cv     = (const float*)d_in[4];
    const float* icos   = (const float*)d_in[5];
    const float* isin   = (const float*)d_in[6];
    const float* tcos   = (const float*)d_in[7];
    const float* tsin   = (const float*)d_in[8];
    const float* Wq     = (const float*)d_in[9];
    const float* bq     = (const float*)d_in[10];
    const float* Wk     = (const float*)d_in[11];
    const float* bk     = (const float*)d_in[12];
    const float* Wv     = (const float*)d_in[13];
    const float* bv     = (const float*)d_in[14];
    const float* Wq_add = (const float*)d_in[15];
    const float* bq_add = (const float*)d_in[16];
    const float* Wk_add = (const float*)d_in[17];
    const float* bk_add = (const float*)d_in[18];
    const float* Wv_add = (const float*)d_in[19];
    const float* bv_add = (const float*)d_in[20];
    const float* nqw    = (const float*)d_in[21];
    const float* nkw    = (const float*)d_in[22];
    const float* naqw   = (const float*)d_in[23];
    const float* nakw   = (const float*)d_in[24];
    const float* Wo     = (const float*)d_in[25];
    const float* bo     = (const float*)d_in[26];
    const float* Wo_add = (const float*)d_in[27];
    const float* bo_add = (const float*)d_in[28];
    float* out = (float*)d_out;

    float *Qb, *Kb, *Vb, *Ob;
    cudaGetSymbolAddress((void**)&Qb, g_Q);
    cudaGetSymbolAddress((void**)&Kb, g_K);
    cudaGetSymbolAddress((void**)&Vb, g_V);
    cudaGetSymbolAddress((void**)&Ob, g_O);
    __nv_bfloat16 *WhT, *WlT, *Ah, *Al, *Eh, *El;
    cudaGetSymbolAddress((void**)&WhT, g_WhT);
    cudaGetSymbolAddress((void**)&WlT, g_WlT);
    cudaGetSymbolAddress((void**)&Ah, g_Ah);
    cudaGetSymbolAddress((void**)&Al, g_Al);
    cudaGetSymbolAddress((void**)&Eh, g_Eh);
    cudaGetSymbolAddress((void**)&El, g_El);

    const size_t attn_smem = (size_t)ATTN_SMEM_FLOATS * sizeof(float);
    cudaFuncSetAttribute(attn_kernel, cudaFuncAttributeMaxDynamicSharedMemorySize,
                         (int)attn_smem);
    cudaFuncSetAttribute(mma_gemm, cudaFuncAttributeMaxDynamicSharedMemorySize,
                         MG_SMEM);

    // cached K/V -> tail of K/V buffers (rows 1280..4351)
    cudaMemcpyAsync(Kb + (size_t)1280 * DMODEL, ck,
                    (size_t)3072 * DMODEL * sizeof(float), cudaMemcpyDeviceToDevice);
    cudaMemcpyAsync(Vb + (size_t)1280 * DMODEL, cv,
                    (size_t)3072 * DMODEL * sizeof(float), cudaMemcpyDeviceToDevice);

    // weight split+transpose: order Wq,Wk,Wv,Wq_add,Wk_add,Wv_add,Wo,Wo_add
    {
        WSrc ws;
        ws.p[0] = Wq;     ws.p[1] = Wk;     ws.p[2] = Wv;
        ws.p[3] = Wq_add; ws.p[4] = Wk_add; ws.p[5] = Wv_add;
        ws.p[6] = Wo;     ws.p[7] = Wo_add;
        convert_hl_T<<<dim3(96, 96, 8), dim3(32, 8)>>>(ws, WhT, WlT);
    }
    // activation splits
    {
        int n4h = 1024 * DMODEL / 4;
        convert_hl<<<(n4h + 255) / 256, 256>>>((const float4*)hidden,
                                               (__nv_bfloat162*)Ah, (__nv_bfloat162*)Al, n4h);
        int n4e = STXT * DMODEL / 4;
        convert_hl<<<(n4e + 255) / 256, 256>>>((const float4*)enc,
                                               (__nv_bfloat162*)Eh, (__nv_bfloat162*)El, n4e);
    }

    // QKV projections (img rows 256..1279 of Q/K/V, txt rows 0..255)
    {
        TGemmSet gi;
        gi.wh[0] = WhT;              gi.wl[0] = WlT;
        gi.wh[1] = WhT + WELEMS;     gi.wl[1] = WlT + WELEMS;
        gi.wh[2] = WhT + 2 * WELEMS; gi.wl[2] = WlT + 2 * WELEMS;
        gi.b[0] = bq; gi.b[1] = bk; gi.b[2] = bv;
        gi.c[0] = Qb + (size_t)256 * DMODEL;
        gi.c[1] = Kb + (size_t)256 * DMODEL;
        gi.c[2] = Vb + (size_t)256 * DMODEL;
        mma_gemm<<<dim3(24, 8, 3), 256, MG_SMEM>>>(Ah, Al, gi);

        TGemmSet gt;
        gt.wh[0] = WhT + 3 * WELEMS; gt.wl[0] = WlT + 3 * WELEMS;
        gt.wh[1] = WhT + 4 * WELEMS; gt.wl[1] = WlT + 4 * WELEMS;
        gt.wh[2] = WhT + 5 * WELEMS; gt.wl[2] = WlT + 5 * WELEMS;
        gt.b[0] = bq_add; gt.b[1] = bk_add; gt.b[2] = bv_add;
        gt.c[0] = Qb; gt.c[1] = Kb; gt.c[2] = Vb;
        mma_gemm<<<dim3(24, 2, 3), 256, MG_SMEM>>>(Eh, El, gt);
    }

    // RMSNorm + RoPE (attention scale folded into Q)
    const float qscale = 0.08838834764831845f; // 1/sqrt(128)
    dim3 nb(32, 8);
    {
        int tot = LQ * NHEAD;
        normrope_kernel<<<(tot + 7) / 8, nb>>>(Qb, LQ, naqw, nqw,
                                               tcos, tsin, icos, isin, qscale);
    }
    {
        int tot = SKV * NHEAD;
        normrope_kernel<<<(tot + 7) / 8, nb>>>(Kb, SKV, nakw, nkw,
                                               tcos, tsin, icos, isin, 1.0f);
    }

    // attention
    attn_kernel<<<dim3(LQ / 64, NHEAD), 256, attn_smem>>>(Qb, Kb, Vb, mask, Ob);

    // split attention output, then output projections
    {
        int n4o = LQ * DMODEL / 4;
        convert_hl<<<(n4o + 255) / 256, 256>>>((const float4*)Ob,
                                               (__nv_bfloat162*)Ah, (__nv_bfloat162*)Al, n4o);
        TGemmSet go;
        go.wh[0] = WhT + 6 * WELEMS; go.wl[0] = WlT + 6 * WELEMS;
        go.wh[1] = go.wh[0];         go.wl[1] = go.wl[0];
        go.wh[2] = go.wh[0];         go.wl[2] = go.wl[0];
        go.b[0] = bo; go.b[1] = bo; go.b[2] = bo;
        go.c[0] = out; go.c[1] = out; go.c[2] = out;
        mma_gemm<<<dim3(24, 8, 1), 256, MG_SMEM>>>(Ah + (size_t)256 * DMODEL,
                                                   Al + (size_t)256 * DMODEL, go);
        TGemmSet ga;
        ga.wh[0] = WhT + 7 * WELEMS; ga.wl[0] = WlT + 7 * WELEMS;
        ga.wh[1] = ga.wh[0];         ga.wl[1] = ga.wl[0];
        ga.wh[2] = ga.wh[0];         ga.wl[2] = ga.wl[0];
        ga.b[0] = bo_add; ga.b[1] = bo_add; ga.b[2] = bo_add;
        float* outt = out + (size_t)1024 * DMODEL;
        ga.c[0] = outt; ga.c[1] = outt; ga.c[2] = outt;
        mma_gemm<<<dim3(24, 2, 1), 256, MG_SMEM>>>(Ah, Al, ga);
    }
}

// round 5
// speedup vs baseline: 7.3062x; 2.3904x over previous
#include <cuda_runtime.h>
#include <cuda_bf16.h>
#include <math.h>
#include <stdint.h>

#define DMODEL 3072
#define NHEAD  24
#define HD     128
#define LQ     1280     // 256 txt + 1024 img queries
#define SKV    4352     // 256 txt + 1024 den + 3072 cached
#define STXT   256

// ---------------- scratch (device globals: allocation-free) ----------------
__device__ float g_Q[(size_t)LQ  * DMODEL];
__device__ float g_K[(size_t)SKV * DMODEL];
__device__ float g_V[(size_t)SKV * DMODEL];

// bf16 hi/lo split buffers
#define WELEMS ((size_t)DMODEL * DMODEL)
__device__ __nv_bfloat16 g_WhT[8 * WELEMS];   // transposed [N][K], hi
__device__ __nv_bfloat16 g_WlT[8 * WELEMS];   // transposed [N][K], lo
__device__ __nv_bfloat16 g_Ah[(size_t)LQ * DMODEL];   // act hi / Q hi / O hi
__device__ __nv_bfloat16 g_Al[(size_t)LQ * DMODEL];   // act lo / Q lo / O lo
__device__ __nv_bfloat16 g_Eh[(size_t)STXT * DMODEL];
__device__ __nv_bfloat16 g_El[(size_t)STXT * DMODEL];
__device__ __nv_bfloat16 g_Kh[(size_t)SKV * DMODEL];
__device__ __nv_bfloat16 g_Kl[(size_t)SKV * DMODEL];
__device__ __nv_bfloat16 g_Vh[(size_t)SKV * DMODEL];
__device__ __nv_bfloat16 g_Vl[(size_t)SKV * DMODEL];

// ---------------- PTX helpers -----------------------------------------------
__device__ __forceinline__ void cp_async16(unsigned dst, const void* src) {
    asm volatile("cp.async.cg.shared.global [%0], [%1], 16;" :: "r"(dst), "l"(src));
}
__device__ __forceinline__ void cp_commit() {
    asm volatile("cp.async.commit_group;");
}
template<int N> __device__ __forceinline__ void cp_wait() {
    asm volatile("cp.async.wait_group %0;" :: "n"(N));
}
__device__ __forceinline__ uint32_t smem_u32(const void* p) {
    uint32_t a;
    asm("{ .reg .u64 t; cvta.to.shared.u64 t, %1; cvt.u32.u64 %0, t; }" : "=r"(a) : "l"(p));
    return a;
}

#define LDSM_X4(r0, r1, r2, r3, addr)                                           \
    asm volatile("ldmatrix.sync.aligned.m8n8.x4.shared.b16 {%0,%1,%2,%3}, [%4];" \
        : "=r"(r0), "=r"(r1), "=r"(r2), "=r"(r3) : "r"(addr))

#define LDSM_X4_T(r0, r1, r2, r3, addr)                                         \
    asm volatile("ldmatrix.sync.aligned.m8n8.x4.trans.shared.b16 {%0,%1,%2,%3}, [%4];" \
        : "=r"(r0), "=r"(r1), "=r"(r2), "=r"(r3) : "r"(addr))

#define MMA16816(d, a0, a1, a2, a3, b0, b1)                                     \
    asm volatile("mma.sync.aligned.m16n8k16.row.col.f32.bf16.bf16.f32 "         \
        "{%0,%1,%2,%3},{%4,%5,%6,%7},{%8,%9},{%0,%1,%2,%3};"                    \
        : "+f"((d)[0]), "+f"((d)[1]), "+f"((d)[2]), "+f"((d)[3])                \
        : "r"(a0), "r"(a1), "r"(a2), "r"(a3), "r"(b0), "r"(b1))

__device__ __forceinline__ uint32_t packbf(float lo, float hi) {
    uint32_t r;
    asm("cvt.rn.bf16x2.f32 %0, %1, %2;" : "=r"(r) : "f"(hi), "f"(lo));
    return r;
}
__device__ __forceinline__ float bfhi(float x) {
    return __bfloat162float(__float2bfloat16(x));
}

// ---------------- conversion kernels ----------------------------------------
__global__ void convert_hl(const float4* __restrict__ X,
                           __nv_bfloat162* __restrict__ H,
                           __nv_bfloat162* __restrict__ L, int n4)
{
    int i = blockIdx.x * 256 + threadIdx.x;
    if (i >= n4) return;
    float4 v = X[i];
    __nv_bfloat16 h0 = __float2bfloat16(v.x);
    __nv_bfloat16 h1 = __float2bfloat16(v.y);
    __nv_bfloat16 h2 = __float2bfloat16(v.z);
    __nv_bfloat16 h3 = __float2bfloat16(v.w);
    __nv_bfloat16 l0 = __float2bfloat16(v.x - __bfloat162float(h0));
    __nv_bfloat16 l1 = __float2bfloat16(v.y - __bfloat162float(h1));
    __nv_bfloat16 l2 = __float2bfloat16(v.z - __bfloat162float(h2));
    __nv_bfloat16 l3 = __float2bfloat16(v.w - __bfloat162float(h3));
    H[2 * i]     = __nv_bfloat162(h0, h1);
    H[2 * i + 1] = __nv_bfloat162(h2, h3);
    L[2 * i]     = __nv_bfloat162(l0, l1);
    L[2 * i + 1] = __nv_bfloat162(l2, l3);
}

// split + transpose 8 weight matrices: W[K][N] fp32 -> WhT/WlT[N][K] bf16
struct WSrc { const float* p[8]; };

__global__ void convert_hl_T(WSrc ws, __nv_bfloat16* __restrict__ Ht,
                             __nv_bfloat16* __restrict__ Lt)
{
    __shared__ float tile[32][33];
    const int mtx = blockIdx.z;
    const float* __restrict__ W = ws.p[mtx];
    const size_t base = (size_t)mtx * WELEMS;
    const int tx = threadIdx.x;
    const int ty = threadIdx.y;
    const int n0 = blockIdx.x * 32;
    const int k0 = blockIdx.y * 32;
#pragma unroll
    for (int i = 0; i < 4; i++)
        tile[ty + 8 * i][tx] = W[(size_t)(k0 + ty + 8 * i) * DMODEL + n0 + tx];
    __syncthreads();
#pragma unroll
    for (int i = 0; i < 4; i++) {
        float x = tile[tx][ty + 8 * i];
        __nv_bfloat16 h = __float2bfloat16(x);
        __nv_bfloat16 l = __float2bfloat16(x - __bfloat162float(h));
        size_t ofs = base + (size_t)(n0 + ty + 8 * i) * DMODEL + k0 + tx;
        Ht[ofs] = h;
        Lt[ofs] = l;
    }
}

// ---------------- mma.sync bf16 hi/lo GEMM (unchanged, validated) ------------
struct TGemmSet {
    const __nv_bfloat16 *wh[3], *wl[3];
    const float* b[3];
    float* c[3];
};

#define SUB_ELEMS   (128 * 40)
#define STAGE_ELEMS (4 * SUB_ELEMS)
#define STAGE_BYTES (STAGE_ELEMS * 2)
#define MG_SMEM     (2 * STAGE_BYTES)

__device__ __forceinline__ void mg_load_stage(
    uint32_t sb, int stage,
    const __nv_bfloat16* __restrict__ Ah, const __nv_bfloat16* __restrict__ Al,
    const __nv_bfloat16* __restrict__ Wh, const __nv_bfloat16* __restrict__ Wl,
    int m0, int n0, int k0, int t)
{
    const uint32_t s0 = sb + stage * STAGE_BYTES;
#pragma unroll
    for (int c = t; c < 512; c += 256) {
        const int row = c >> 2;
        const int ch  = (c & 3) * 8;
        const uint32_t d = s0 + (row * 40 + ch) * 2;
        const size_t ga = (size_t)(m0 + row) * DMODEL + k0 + ch;
        const size_t gb = (size_t)(n0 + row) * DMODEL + k0 + ch;
        cp_async16(d,                     Ah + ga);
        cp_async16(d + 1 * SUB_ELEMS * 2, Al + ga);
        cp_async16(d + 2 * SUB_ELEMS * 2, Wh + gb);
        cp_async16(d + 3 * SUB_ELEMS * 2, Wl + gb);
    }
    cp_commit();
}

__global__ __launch_bounds__(256) void mma_gemm(
    const __nv_bfloat16* __restrict__ Ah,
    const __nv_bfloat16* __restrict__ Al, TGemmSet gs)
{
    extern __shared__ __align__(128) __nv_bfloat16 smg[];
    const uint32_t sb = smem_u32(smg);

    const int z = blockIdx.z;
    const __nv_bfloat16* __restrict__ Wh = gs.wh[z];
    const __nv_bfloat16* __restrict__ Wl = gs.wl[z];
    const float* __restrict__ bias = gs.b[z];
    float* __restrict__ C = gs.c[z];

    const int t    = threadIdx.x;
    const int wid  = t >> 5;
    const int lane = t & 31;
    const int wm   = wid >> 2;
    const int wn   = wid & 3;
    const int m0   = blockIdx.y * 128;
    const int n0   = blockIdx.x * 128;

    const int mat = lane >> 3, r = lane & 7;
    int aOff[4], bOff[2];
#pragma unroll
    for (int i = 0; i < 4; i++)
        aOff[i] = (wm * 64 + 16 * i + (mat & 1) * 8 + r) * 40 + (mat >> 1) * 8;
#pragma unroll
    for (int p = 0; p < 2; p++)
        bOff[p] = (wn * 32 + 16 * p + (mat >> 1) * 8 + r) * 40 + (mat & 1) * 8;

    float acc[4][4][4];
#pragma unroll
    for (int i = 0; i < 4; i++)
#pragma unroll
        for (int j = 0; j < 4; j++)
#pragma unroll
            for (int q = 0; q < 4; q++) acc[i][j][q] = 0.f;

    const int NS = DMODEL / 32;
    mg_load_stage(sb, 0, Ah, Al, Wh, Wl, m0, n0, 0,  t);
    mg_load_stage(sb, 1, Ah, Al, Wh, Wl, m0, n0, 32, t);

    for (int s = 0; s < NS; s++) {
        if (s + 1 < NS) cp_wait<1>(); else cp_wait<0>();
        __syncthreads();
        const uint32_t s0 = sb + (s & 1) * STAGE_BYTES;

#pragma unroll
        for (int ks = 0; ks < 2; ks++) {
            const int ke = ks * 16;
            uint32_t ah[4][4], al[4][4], bh[2][4], bl[2][4];
#pragma unroll
            for (int i = 0; i < 4; i++) {
                LDSM_X4(ah[i][0], ah[i][1], ah[i][2], ah[i][3],
                        s0 + (aOff[i] + ke) * 2);
                LDSM_X4(al[i][0], al[i][1], al[i][2], al[i][3],
                        s0 + 1 * SUB_ELEMS * 2 + (aOff[i] + ke) * 2);
            }
#pragma unroll
            for (int p = 0; p < 2; p++) {
                LDSM_X4(bh[p][0], bh[p][1], bh[p][2], bh[p][3],
                        s0 + 2 * SUB_ELEMS * 2 + (bOff[p] + ke) * 2);
                LDSM_X4(bl[p][0], bl[p][1], bl[p][2], bl[p][3],
                        s0 + 3 * SUB_ELEMS * 2 + (bOff[p] + ke) * 2);
            }
#pragma unroll
            for (int i = 0; i < 4; i++)
#pragma unroll
                for (int j = 0; j < 4; j++) {
                    const int p = j >> 1, q = (j & 1) * 2;
                    MMA16816(acc[i][j], ah[i][0], ah[i][1], ah[i][2], ah[i][3],
                             bh[p][q], bh[p][q + 1]);
                    MMA16816(acc[i][j], ah[i][0], ah[i][1], ah[i][2], ah[i][3],
                             bl[p][q], bl[p][q + 1]);
                    MMA16816(acc[i][j], al[i][0], al[i][1], al[i][2], al[i][3],
                             bh[p][q], bh[p][q + 1]);
                }
        }
        __syncthreads();
        if (s + 2 < NS)
            mg_load_stage(sb, s & 1, Ah, Al, Wh, Wl, m0, n0, (s + 2) * 32, t);
    }

    const int r4 = lane >> 2;
    const int c2 = (lane & 3) * 2;
#pragma unroll
    for (int i = 0; i < 4; i++) {
        const int grow = m0 + wm * 64 + 16 * i + r4;
#pragma unroll
        for (int j = 0; j < 4; j++) {
            const int gcol = n0 + wn * 32 + 8 * j + c2;
            const float b0 = bias[gcol], b1 = bias[gcol + 1];
            float2 v0, v1;
            v0.x = acc[i][j][0] + b0; v0.y = acc[i][j][1] + b1;
            v1.x = acc[i][j][2] + b0; v1.y = acc[i][j][3] + b1;
            *(float2*)(C + (size_t)grow * DMODEL + gcol)       = v0;
            *(float2*)(C + (size_t)(grow + 8) * DMODEL + gcol) = v1;
        }
    }
}

// ---------------- RMSNorm + RoPE -> bf16 hi/lo --------------------------------
__global__ void normrope_hl(
    const float* __restrict__ X, int rows,
    const float* __restrict__ w_txt, const float* __restrict__ w_img,
    const float* __restrict__ tcos, const float* __restrict__ tsin,
    const float* __restrict__ icos, const float* __restrict__ isin,
    float outscale,
    __nv_bfloat162* __restrict__ H, __nv_bfloat162* __restrict__ L)
{
    const int id   = blockIdx.x * blockDim.y + threadIdx.y;
    const int lane = threadIdx.x;
    if (id >= rows * NHEAD) return;
    const int row = id / NHEAD;
    const int h   = id % NHEAD;

    const float2* p2 = (const float2*)(X + (size_t)row * DMODEL + h * HD);
    float2 v0 = p2[lane];
    float2 v1 = p2[lane + 32];

    float ss = v0.x * v0.x + v0.y * v0.y + v1.x * v1.x + v1.y * v1.y;
#pragma unroll
    for (int o = 16; o > 0; o >>= 1) ss += __shfl_xor_sync(0xffffffffu, ss, o);
    const float rms = rsqrtf(ss * (1.0f / 128.0f) + 1e-6f);

    const float *w, *cT, *sT;
    if (row < STXT) { w = w_txt; cT = tcos + (size_t)row * 64;          sT = tsin + (size_t)row * 64; }
    else            { w = w_img; cT = icos + (size_t)(row - STXT) * 64; sT = isin + (size_t)(row - STXT) * 64; }

    const size_t ob = ((size_t)row * DMODEL + h * HD) / 2;
#pragma unroll
    for (int half = 0; half < 2; half++) {
        const int p = lane + 32 * half;
        const float2 v = half ? v1 : v0;
        float c = cT[p], s = sT[p];
        float yr = v.x * rms * w[2 * p];
        float yi = v.y * rms * w[2 * p + 1];
        float o0 = (yr * c - yi * s) * outscale;
        float o1 = (yr * s + yi * c) * outscale;
        __nv_bfloat16 h0 = __float2bfloat16(o0);
        __nv_bfloat16 h1 = __float2bfloat16(o1);
        __nv_bfloat16 l0 = __float2bfloat16(o0 - __bfloat162float(h0));
        __nv_bfloat16 l1 = __float2bfloat16(o1 - __bfloat162float(h1));
        H[ob + p] = __nv_bfloat162(h0, h1);
        L[ob + p] = __nv_bfloat162(l0, l1);
    }
}

// ---------------- Flash attention v3: bf16 hi/lo mma.sync --------------------
// 64q x 64kv tiles, 4 warps (16 q rows each), online softmax in registers.
#define AST     136                 // bf16 row stride (272B; 272%128=16 -> conflict-free)
#define AMAT    (64 * AST)          // elems per matrix
#define ASTB    (AMAT * 2)          // bytes per matrix (17408)
#define ASTAGEB (4 * ASTB)          // Kh|Kl|Vh|Vl stage bytes (69632)
#define ATTN3_SMEM (2 * ASTAGEB + 1024)

__global__ __launch_bounds__(128) void attn3(
    const __nv_bfloat16* __restrict__ Qh, const __nv_bfloat16* __restrict__ Ql,
    const __nv_bfloat16* __restrict__ Kh, const __nv_bfloat16* __restrict__ Kl,
    const __nv_bfloat16* __restrict__ Vh, const __nv_bfloat16* __restrict__ Vl,
    const int* __restrict__ mask,
    __nv_bfloat16* __restrict__ Oh, __nv_bfloat16* __restrict__ Ol)
{
    extern __shared__ __align__(16) char sm3[];
    const uint32_t sbase = smem_u32(sm3);
    float* mb = (float*)(sm3 + 2 * ASTAGEB);

    const int t    = threadIdx.x;
    const int wid  = t >> 5;
    const int lane = t & 31;
    const int h    = blockIdx.y;
    const int q0   = blockIdx.x * 64;
    const int hcol = h * HD;

    const int gr = lane >> 2, ct = lane & 3;
    const int mat = lane >> 3, r = lane & 7;
    const int bRow = ((mat >> 1) << 3) + r;   // K (non-trans) ldmatrix row sel
    const int bCol = (mat & 1) << 3;
    const int vRow = ((mat & 1) << 3) + r;    // V (trans) ldmatrix row sel
    const int vCol = (mat >> 1) << 3;

    // mask bias
    for (int i = t; i < STXT; i += 128)
        mb[i] = (mask[i] == 0) ? -1e30f : 0.f;

    // Q fragments (registers, loaded once)
    uint32_t qh[8][4], ql[8][4];
    {
        const size_t r0 = (size_t)(q0 + wid * 16 + gr) * DMODEL + hcol;
        const size_t r1 = r0 + 8 * DMODEL;
#pragma unroll
        for (int c = 0; c < 8; c++) {
            const int col = 16 * c + 2 * ct;
            qh[c][0] = *(const uint32_t*)(Qh + r0 + col);
            qh[c][1] = *(const uint32_t*)(Qh + r1 + col);
            qh[c][2] = *(const uint32_t*)(Qh + r0 + col + 8);
            qh[c][3] = *(const uint32_t*)(Qh + r1 + col + 8);
            ql[c][0] = *(const uint32_t*)(Ql + r0 + col);
            ql[c][1] = *(const uint32_t*)(Ql + r1 + col);
            ql[c][2] = *(const uint32_t*)(Ql + r0 + col + 8);
            ql[c][3] = *(const uint32_t*)(Ql + r1 + col + 8);
        }
    }

    float o[16][4];
#pragma unroll
    for (int j = 0; j < 16; j++)
#pragma unroll
        for (int e = 0; e < 4; e++) o[j][e] = 0.f;
    float m0 = -INFINITY, m1 = -INFINITY, l0 = 0.f, l1 = 0.f;

#define ISSUE_KV3(st, kb)                                                         \
    {                                                                             \
        _Pragma("unroll")                                                         \
        for (int c = t; c < 4096; c += 128) {                                     \
            const int mtx = c >> 10;                                              \
            const int rem = c & 1023;                                             \
            const int row = rem >> 4;                                             \
            const int ch  = (rem & 15) * 8;                                       \
            const __nv_bfloat16* src = (mtx == 0) ? Kh : (mtx == 1) ? Kl          \
                                     : (mtx == 2) ? Vh : Vl;                      \
            cp_async16(sbase + (st) * ASTAGEB + mtx * ASTB + (row * AST + ch) * 2,\
                       src + (size_t)((kb) + row) * DMODEL + hcol + ch);          \
        }                                                                         \
        cp_commit();                                                              \
    }

    const int NT = SKV / 64;   // 68
    ISSUE_KV3(0, 0)

    for (int kt = 0; kt < NT; kt++) {
        const int kb = kt * 64;
        if (kt + 1 < NT) {
            ISSUE_KV3((kt + 1) & 1, (kt + 1) * 64)
            cp_wait<1>();
        } else {
            cp_wait<0>();
        }
        __syncthreads();
        const uint32_t stg = sbase + (kt & 1) * ASTAGEB;

        // ---- QK ----
        float s[8][4];
#pragma unroll
        for (int j = 0; j < 8; j++)
#pragma unroll
            for (int e = 0; e < 4; e++) s[j][e] = 0.f;

#pragma unroll
        for (int c = 0; c < 8; c++) {
#pragma unroll
            for (int g2 = 0; g2 < 4; g2++) {
                uint32_t kh0, kh1, kh2, kh3, kl0, kl1, kl2, kl3;
                const uint32_t a = stg +
                    (((g2 * 16 + bRow) * AST + 16 * c + bCol) << 1);
                LDSM_X4(kh0, kh1, kh2, kh3, a);
                LDSM_X4(kl0, kl1, kl2, kl3, a + ASTB);
                MMA16816(s[2 * g2], qh[c][0], qh[c][1], qh[c][2], qh[c][3], kh0, kh1);
                MMA16816(s[2 * g2], qh[c][0], qh[c][1], qh[c][2], qh[c][3], kl0, kl1);
                MMA16816(s[2 * g2], ql[c][0], ql[c][1], ql[c][2], ql[c][3], kh0, kh1);
                MMA16816(s[2 * g2 + 1], qh[c][0], qh[c][1], qh[c][2], qh[c][3], kh2, kh3);
                MMA16816(s[2 * g2 + 1], qh[c][0], qh[c][1], qh[c][2], qh[c][3], kl2, kl3);
                MMA16816(s[2 * g2 + 1], ql[c][0], ql[c][1], ql[c][2], ql[c][3], kh2, kh3);
            }
        }

        if (kb < STXT) {
#pragma unroll
            for (int j = 0; j < 8; j++) {
                const int col = kb + 8 * j + 2 * ct;
                const float b0 = mb[col], b1 = mb[col + 1];
                s[j][0] += b0; s[j][1] += b1;
                s[j][2] += b0; s[j][3] += b1;
            }
        }

        // ---- online softmax (register-resident) ----
        float tm0 = -1e30f, tm1 = -1e30f;
#pragma unroll
        for (int j = 0; j < 8; j++) {
            tm0 = fmaxf(tm0, fmaxf(s[j][0], s[j][1]));
            tm1 = fmaxf(tm1, fmaxf(s[j][2], s[j][3]));
        }
        tm0 = fmaxf(tm0, __shfl_xor_sync(0xffffffffu, tm0, 1));
        tm0 = fmaxf(tm0, __shfl_xor_sync(0xffffffffu, tm0, 2));
        tm1 = fmaxf(tm1, __shfl_xor_sync(0xffffffffu, tm1, 1));
        tm1 = fmaxf(tm1, __shfl_xor_sync(0xffffffffu, tm1, 2));
        const float mn0 = fmaxf(m0, tm0), mn1 = fmaxf(m1, tm1);
        const float c0 = __expf(m0 - mn0), c1 = __expf(m1 - mn1);
        l0 *= c0; l1 *= c1;
#pragma unroll
        for (int j = 0; j < 16; j++) {
            o[j][0] *= c0; o[j][1] *= c0;
            o[j][2] *= c1; o[j][3] *= c1;
        }
        float s0 = 0.f, s1 = 0.f;
#pragma unroll
        for (int j = 0; j < 8; j++) {
            s[j][0] = __expf(s[j][0] - mn0);
            s[j][1] = __expf(s[j][1] - mn0);
            s[j][2] = __expf(s[j][2] - mn1);
            s[j][3] = __expf(s[j][3] - mn1);
            s0 += s[j][0] + s[j][1];
            s1 += s[j][2] + s[j][3];
        }
        s0 += __shfl_xor_sync(0xffffffffu, s0, 1);
        s0 += __shfl_xor_sync(0xffffffffu, s0, 2);
        s1 += __shfl_xor_sync(0xffffffffu, s1, 1);
        s1 += __shfl_xor_sync(0xffffffffu, s1, 2);
        l0 += s0; l1 += s1;
        m0 = mn0; m1 = mn1;

        // ---- pack P to bf16 hi/lo A-fragments ----
        uint32_t ph[4][4], pl[4][4];
#pragma unroll
        for (int mm = 0; mm < 4; mm++) {
            const int j0 = 2 * mm, j1 = 2 * mm + 1;
            ph[mm][0] = packbf(s[j0][0], s[j0][1]);
            ph[mm][1] = packbf(s[j0][2], s[j0][3]);
            ph[mm][2] = packbf(s[j1][0], s[j1][1]);
            ph[mm][3] = packbf(s[j1][2], s[j1][3]);
            pl[mm][0] = packbf(s[j0][0] - bfhi(s[j0][0]), s[j0][1] - bfhi(s[j0][1]));
            pl[mm][1] = packbf(s[j0][2] - bfhi(s[j0][2]), s[j0][3] - bfhi(s[j0][3]));
            pl[mm][2] = packbf(s[j1][0] - bfhi(s[j1][0]), s[j1][1] - bfhi(s[j1][1]));
            pl[mm][3] = packbf(s[j1][2] - bfhi(s[j1][2]), s[j1][3] - bfhi(s[j1][3]));
        }

        // ---- PV ----
#pragma unroll
        for (int mm = 0; mm < 4; mm++) {
#pragma unroll
            for (int g = 0; g < 8; g++) {
                uint32_t vh0, vh1, vh2, vh3, vl0, vl1, vl2, vl3;
                const uint32_t a = stg + 2 * ASTB +
                    (((16 * mm + vRow) * AST + 16 * g + vCol) << 1);
                LDSM_X4_T(vh0, vh1, vh2, vh3, a);
                LDSM_X4_T(vl0, vl1, vl2, vl3, a + ASTB);
                MMA16816(o[2 * g], ph[mm][0], ph[mm][1], ph[mm][2], ph[mm][3], vh0, vh1);
                MMA16816(o[2 * g], ph[mm][0], ph[mm][1], ph[mm][2], ph[mm][3], vl0, vl1);
                MMA16816(o[2 * g], pl[mm][0], pl[mm][1], pl[mm][2], pl[mm][3], vh0, vh1);
                MMA16816(o[2 * g + 1], ph[mm][0], ph[mm][1], ph[mm][2], ph[mm][3], vh2, vh3);
                MMA16816(o[2 * g + 1], ph[mm][0], ph[mm][1], ph[mm][2], ph[mm][3], vl2, vl3);
                MMA16816(o[2 * g + 1], pl[mm][0], pl[mm][1], pl[mm][2], pl[mm][3], vh2, vh3);
            }
        }
        __syncthreads();
    }
#undef ISSUE_KV3

    // ---- epilogue: O /= l, write bf16 hi/lo ----
    const float inv0 = 1.0f / l0, inv1 = 1.0f / l1;
    const size_t r0 = (size_t)(q0 + wid * 16 + gr) * DMODEL + hcol;
    const size_t r1 = r0 + 8 * DMODEL;
#pragma unroll
    for (int j = 0; j < 16; j++) {
        const int col = 8 * j + 2 * ct;
        const float f0 = o[j][0] * inv0, f1 = o[j][1] * inv0;
        const float f2 = o[j][2] * inv1, f3 = o[j][3] * inv1;
        *(uint32_t*)(Oh + r0 + col) = packbf(bfhi(f0), bfhi(f1));
        *(uint32_t*)(Ol + r0 + col) = packbf(f0 - bfhi(f0), f1 - bfhi(f1));
        *(uint32_t*)(Oh + r1 + col) = packbf(bfhi(f2), bfhi(f3));
        *(uint32_t*)(Ol + r1 + col) = packbf(f2 - bfhi(f2), f3 - bfhi(f3));
    }
}

// ---------------- launch -----------------------------------------------------
extern "C" void kernel_launch(void* const* d_in, const int* in_sizes, int n_in,
                              void* d_out, int out_size)
{
    const float* hidden = (const float*)d_in[0];
    const float* enc    = (const float*)d_in[1];
    const int*   mask   = (const int*)  d_in[2];
    const float* ck     = (const float*)d_in[3];
    const float* cv     = (const float*)d_in[4];
    const float* icos   = (const float*)d_in[5];
    const float* isin   = (const float*)d_in[6];
    const float* tcos   = (const float*)d_in[7];
    const float* tsin   = (const float*)d_in[8];
    const float* Wq     = (const float*)d_in[9];
    const float* bq     = (const float*)d_in[10];
    const float* Wk     = (const float*)d_in[11];
    const float* bk     = (const float*)d_in[12];
    const float* Wv     = (const float*)d_in[13];
    const float* bv     = (const float*)d_in[14];
    const float* Wq_add = (const float*)d_in[15];
    const float* bq_add = (const float*)d_in[16];
    const float* Wk_add = (const float*)d_in[17];
    const float* bk_add = (const float*)d_in[18];
    const float* Wv_add = (const float*)d_in[19];
    const float* bv_add = (const float*)d_in[20];
    const float* nqw    = (const float*)d_in[21];
    const float* nkw    = (const float*)d_in[22];
    const float* naqw   = (const float*)d_in[23];
    const float* nakw   = (const float*)d_in[24];
    const float* Wo     = (const float*)d_in[25];
    const float* bo     = (const float*)d_in[26];
    const float* Wo_add = (const float*)d_in[27];
    const float* bo_add = (const float*)d_in[28];
    float* out = (float*)d_out;

    float *Qb, *Kb, *Vb;
    cudaGetSymbolAddress((void**)&Qb, g_Q);
    cudaGetSymbolAddress((void**)&Kb, g_K);
    cudaGetSymbolAddress((void**)&Vb, g_V);
    __nv_bfloat16 *WhT, *WlT, *Ah, *Al, *Eh, *El, *Khb, *Klb, *Vhb, *Vlb;
    cudaGetSymbolAddress((void**)&WhT, g_WhT);
    cudaGetSymbolAddress((void**)&WlT, g_WlT);
    cudaGetSymbolAddress((void**)&Ah, g_Ah);
    cudaGetSymbolAddress((void**)&Al, g_Al);
    cudaGetSymbolAddress((void**)&Eh, g_Eh);
    cudaGetSymbolAddress((void**)&El, g_El);
    cudaGetSymbolAddress((void**)&Khb, g_Kh);
    cudaGetSymbolAddress((void**)&Klb, g_Kl);
    cudaGetSymbolAddress((void**)&Vhb, g_Vh);
    cudaGetSymbolAddress((void**)&Vlb, g_Vl);

    cudaFuncSetAttribute(mma_gemm, cudaFuncAttributeMaxDynamicSharedMemorySize,
                         MG_SMEM);
    cudaFuncSetAttribute(attn3, cudaFuncAttributeMaxDynamicSharedMemorySize,
                         ATTN3_SMEM);

    // cached K -> tail of fp32 K buffer (rows 1280..4351); V handled via convert
    cudaMemcpyAsync(Kb + (size_t)1280 * DMODEL, ck,
                    (size_t)3072 * DMODEL * sizeof(float), cudaMemcpyDeviceToDevice);

    // weight split+transpose
    {
        WSrc ws;
        ws.p[0] = Wq;     ws.p[1] = Wk;     ws.p[2] = Wv;
        ws.p[3] = Wq_add; ws.p[4] = Wk_add; ws.p[5] = Wv_add;
        ws.p[6] = Wo;     ws.p[7] = Wo_add;
        convert_hl_T<<<dim3(96, 96, 8), dim3(32, 8)>>>(ws, WhT, WlT);
    }
    // activation splits
    {
        int n4h = 1024 * DMODEL / 4;
        convert_hl<<<(n4h + 255) / 256, 256>>>((const float4*)hidden,
                                               (__nv_bfloat162*)Ah, (__nv_bfloat162*)Al, n4h);
        int n4e = STXT * DMODEL / 4;
        convert_hl<<<(n4e + 255) / 256, 256>>>((const float4*)enc,
                                               (__nv_bfloat162*)Eh, (__nv_bfloat162*)El, n4e);
    }

    // QKV projections (img rows 256..1279, txt rows 0..255) -> fp32 Q/K/V
    {
        TGemmSet gi;
        gi.wh[0] = WhT;              gi.wl[0] = WlT;
        gi.wh[1] = WhT + WELEMS;     gi.wl[1] = WlT + WELEMS;
        gi.wh[2] = WhT + 2 * WELEMS; gi.wl[2] = WlT + 2 * WELEMS;
        gi.b[0] = bq; gi.b[1] = bk; gi.b[2] = bv;
        gi.c[0] = Qb + (size_t)256 * DMODEL;
        gi.c[1] = Kb + (size_t)256 * DMODEL;
        gi.c[2] = Vb + (size_t)256 * DMODEL;
        mma_gemm<<<dim3(24, 8, 3), 256, MG_SMEM>>>(Ah, Al, gi);

        TGemmSet gt;
        gt.wh[0] = WhT + 3 * WELEMS; gt.wl[0] = WlT + 3 * WELEMS;
        gt.wh[1] = WhT + 4 * WELEMS; gt.wl[1] = WlT + 4 * WELEMS;
        gt.wh[2] = WhT + 5 * WELEMS; gt.wl[2] = WlT + 5 * WELEMS;
        gt.b[0] = bq_add; gt.b[1] = bk_add; gt.b[2] = bv_add;
        gt.c[0] = Qb; gt.c[1] = Kb; gt.c[2] = Vb;
        mma_gemm<<<dim3(24, 2, 3), 256, MG_SMEM>>>(Eh, El, gt);
    }

    // RMSNorm + RoPE -> bf16 hi/lo (Q into Ah/Al — GEMM inputs are dead now)
    const float qscale = 0.08838834764831845f; // 1/sqrt(128)
    dim3 nb(32, 8);
    {
        int tot = LQ * NHEAD;
        normrope_hl<<<(tot + 7) / 8, nb>>>(Qb, LQ, naqw, nqw,
                                           tcos, tsin, icos, isin, qscale,
                                           (__nv_bfloat162*)Ah, (__nv_bfloat162*)Al);
    }
    {
        int tot = SKV * NHEAD;
        normrope_hl<<<(tot + 7) / 8, nb>>>(Kb, SKV, nakw, nkw,
                                           tcos, tsin, icos, isin, 1.0f,
                                           (__nv_bfloat162*)Khb, (__nv_bfloat162*)Klb);
    }
    // V hi/lo: projected rows 0..1279 + cached rows 1280..4351
    {
        int n4v = 1280 * DMODEL / 4;
        convert_hl<<<(n4v + 255) / 256, 256>>>((const float4*)Vb,
                                               (__nv_bfloat162*)Vhb, (__nv_bfloat162*)Vlb, n4v);
        int n4c = 3072 * DMODEL / 4;
        convert_hl<<<(n4c + 255) / 256, 256>>>((const float4*)cv,
                                               (__nv_bfloat162*)(Vhb + (size_t)1280 * DMODEL),
                                               (__nv_bfloat162*)(Vlb + (size_t)1280 * DMODEL), n4c);
    }

    // attention: reads Q from Ah/Al, writes O (bf16 hi/lo) back into Ah/Al
    attn3<<<dim3(LQ / 64, NHEAD), 128, ATTN3_SMEM>>>(
        Ah, Al, Khb, Klb, Vhb, Vlb, mask, Ah, Al);

    // output projections: img rows -> out[:1024*D], txt rows -> out[1024*D:]
    {
        TGemmSet go;
        go.wh[0] = WhT + 6 * WELEMS; go.wl[0] = WlT + 6 * WELEMS;
        go.wh[1] = go.wh[0];         go.wl[1] = go.wl[0];
        go.wh[2] = go.wh[0];         go.wl[2] = go.wl[0];
        go.b[0] = bo; go.b[1] = bo; go.b[2] = bo;
        go.c[0] = out; go.c[1] = out; go.c[2] = out;
        mma_gemm<<<dim3(24, 8, 1), 256, MG_SMEM>>>(Ah + (size_t)256 * DMODEL,
                                                   Al + (size_t)256 * DMODEL, go);
        TGemmSet ga;
        ga.wh[0] = WhT + 7 * WELEMS; ga.wl[0] = WlT + 7 * WELEMS;
        ga.wh[1] = ga.wh[0];         ga.wl[1] = ga.wl[0];
        ga.wh[2] = ga.wh[0];         ga.wl[2] = ga.wl[0];
        ga.b[0] = bo_add; ga.b[1] = bo_add; ga.b[2] = bo_add;
        float* outt = out + (size_t)1024 * DMODEL;
        ga.c[0] = outt; ga.c[1] = outt; ga.c[2] = outt;
        mma_gemm<<<dim3(24, 2, 1), 256, MG_SMEM>>>(Ah, Al, ga);
    }
}

// round 6
// speedup vs baseline: 8.2316x; 1.1266x over previous
#include <cuda_runtime.h>
#include <cuda_bf16.h>
#include <math.h>
#include <stdint.h>

#define DMODEL 3072
#define NHEAD  24
#define HD     128
#define LQ     1280     // 256 txt + 1024 img queries
#define SKV    4352     // 256 txt + 1024 den + 3072 cached
#define STXT   256

// ---------------- scratch (device globals: allocation-free) ----------------
__device__ float g_Q[(size_t)LQ  * DMODEL];
__device__ float g_K[(size_t)SKV * DMODEL];
__device__ float g_V[(size_t)SKV * DMODEL];

// bf16 hi/lo split buffers
#define WELEMS ((size_t)DMODEL * DMODEL)
__device__ __nv_bfloat16 g_WhT[8 * WELEMS];   // transposed [N][K], hi
__device__ __nv_bfloat16 g_WlT[8 * WELEMS];   // transposed [N][K], lo
__device__ __nv_bfloat16 g_Ah[(size_t)LQ * DMODEL];   // act hi / Q hi / O hi
__device__ __nv_bfloat16 g_Al[(size_t)LQ * DMODEL];   // act lo / Q lo / O lo
__device__ __nv_bfloat16 g_Eh[(size_t)STXT * DMODEL];
__device__ __nv_bfloat16 g_El[(size_t)STXT * DMODEL];
__device__ __nv_bfloat16 g_Kh[(size_t)SKV * DMODEL];
__device__ __nv_bfloat16 g_Kl[(size_t)SKV * DMODEL];
__device__ __nv_bfloat16 g_Vh[(size_t)SKV * DMODEL];
__device__ __nv_bfloat16 g_Vl[(size_t)SKV * DMODEL];

// ---------------- PTX helpers -----------------------------------------------
__device__ __forceinline__ void cp_async16(unsigned dst, const void* src) {
    asm volatile("cp.async.cg.shared.global [%0], [%1], 16;" :: "r"(dst), "l"(src));
}
__device__ __forceinline__ void cp_commit() {
    asm volatile("cp.async.commit_group;");
}
template<int N> __device__ __forceinline__ void cp_wait() {
    asm volatile("cp.async.wait_group %0;" :: "n"(N));
}
__device__ __forceinline__ uint32_t smem_u32(const void* p) {
    uint32_t a;
    asm("{ .reg .u64 t; cvta.to.shared.u64 t, %1; cvt.u32.u64 %0, t; }" : "=r"(a) : "l"(p));
    return a;
}

#define LDSM_X4(r0, r1, r2, r3, addr)                                           \
    asm volatile("ldmatrix.sync.aligned.m8n8.x4.shared.b16 {%0,%1,%2,%3}, [%4];" \
        : "=r"(r0), "=r"(r1), "=r"(r2), "=r"(r3) : "r"(addr))

#define LDSM_X4_T(r0, r1, r2, r3, addr)                                         \
    asm volatile("ldmatrix.sync.aligned.m8n8.x4.trans.shared.b16 {%0,%1,%2,%3}, [%4];" \
        : "=r"(r0), "=r"(r1), "=r"(r2), "=r"(r3) : "r"(addr))

#define MMA16816(d, a0, a1, a2, a3, b0, b1)                                     \
    asm volatile("mma.sync.aligned.m16n8k16.row.col.f32.bf16.bf16.f32 "         \
        "{%0,%1,%2,%3},{%4,%5,%6,%7},{%8,%9},{%0,%1,%2,%3};"                    \
        : "+f"((d)[0]), "+f"((d)[1]), "+f"((d)[2]), "+f"((d)[3])                \
        : "r"(a0), "r"(a1), "r"(a2), "r"(a3), "r"(b0), "r"(b1))

__device__ __forceinline__ uint32_t packbf(float lo, float hi) {
    uint32_t r;
    asm("cvt.rn.bf16x2.f32 %0, %1, %2;" : "=r"(r) : "f"(hi), "f"(lo));
    return r;
}
__device__ __forceinline__ float bfhi(float x) {
    return __bfloat162float(__float2bfloat16(x));
}

// ---------------- conversion kernels ----------------------------------------
__global__ void convert_hl(const float4* __restrict__ X,
                           __nv_bfloat162* __restrict__ H,
                           __nv_bfloat162* __restrict__ L, int n4)
{
    int i = blockIdx.x * 256 + threadIdx.x;
    if (i >= n4) return;
    float4 v = X[i];
    __nv_bfloat16 h0 = __float2bfloat16(v.x);
    __nv_bfloat16 h1 = __float2bfloat16(v.y);
    __nv_bfloat16 h2 = __float2bfloat16(v.z);
    __nv_bfloat16 h3 = __float2bfloat16(v.w);
    __nv_bfloat16 l0 = __float2bfloat16(v.x - __bfloat162float(h0));
    __nv_bfloat16 l1 = __float2bfloat16(v.y - __bfloat162float(h1));
    __nv_bfloat16 l2 = __float2bfloat16(v.z - __bfloat162float(h2));
    __nv_bfloat16 l3 = __float2bfloat16(v.w - __bfloat162float(h3));
    H[2 * i]     = __nv_bfloat162(h0, h1);
    H[2 * i + 1] = __nv_bfloat162(h2, h3);
    L[2 * i]     = __nv_bfloat162(l0, l1);
    L[2 * i + 1] = __nv_bfloat162(l2, l3);
}

// split + transpose 8 weight matrices: W[K][N] fp32 -> WhT/WlT[N][K] bf16
struct WSrc { const float* p[8]; };

__global__ void convert_hl_T(WSrc ws, __nv_bfloat16* __restrict__ Ht,
                             __nv_bfloat16* __restrict__ Lt)
{
    __shared__ float tile[32][33];
    const int mtx = blockIdx.z;
    const float* __restrict__ W = ws.p[mtx];
    const size_t base = (size_t)mtx * WELEMS;
    const int tx = threadIdx.x;
    const int ty = threadIdx.y;
    const int n0 = blockIdx.x * 32;
    const int k0 = blockIdx.y * 32;
#pragma unroll
    for (int i = 0; i < 4; i++)
        tile[ty + 8 * i][tx] = W[(size_t)(k0 + ty + 8 * i) * DMODEL + n0 + tx];
    __syncthreads();
#pragma unroll
    for (int i = 0; i < 4; i++) {
        float x = tile[tx][ty + 8 * i];
        __nv_bfloat16 h = __float2bfloat16(x);
        __nv_bfloat16 l = __float2bfloat16(x - __bfloat162float(h));
        size_t ofs = base + (size_t)(n0 + ty + 8 * i) * DMODEL + k0 + tx;
        Ht[ofs] = h;
        Lt[ofs] = l;
    }
}

// ---------------- mma.sync bf16 hi/lo GEMM (multi-problem z) ------------------
// C[z] = A[z][Mz x 3072] @ W[z][3072 x 3072] + b[z].
// CTA 128x128, BK=32, 8 warps (2x4), warp tile 64x32 of m16n8k16.
struct TGemmSet {
    const __nv_bfloat16 *ah[6], *al[6];
    const __nv_bfloat16 *wh[6], *wl[6];
    const float* b[6];
    float* c[6];
    int ny[6];
};

#define SUB_ELEMS   (128 * 40)
#define STAGE_ELEMS (4 * SUB_ELEMS)
#define STAGE_BYTES (STAGE_ELEMS * 2)
#define MG_SMEM     (2 * STAGE_BYTES)

__device__ __forceinline__ void mg_load_stage(
    uint32_t sb, int stage,
    const __nv_bfloat16* __restrict__ Ah, const __nv_bfloat16* __restrict__ Al,
    const __nv_bfloat16* __restrict__ Wh, const __nv_bfloat16* __restrict__ Wl,
    int m0, int n0, int k0, int t)
{
    const uint32_t s0 = sb + stage * STAGE_BYTES;
#pragma unroll
    for (int c = t; c < 512; c += 256) {
        const int row = c >> 2;
        const int ch  = (c & 3) * 8;
        const uint32_t d = s0 + (row * 40 + ch) * 2;
        const size_t ga = (size_t)(m0 + row) * DMODEL + k0 + ch;
        const size_t gb = (size_t)(n0 + row) * DMODEL + k0 + ch;
        cp_async16(d,                     Ah + ga);
        cp_async16(d + 1 * SUB_ELEMS * 2, Al + ga);
        cp_async16(d + 2 * SUB_ELEMS * 2, Wh + gb);
        cp_async16(d + 3 * SUB_ELEMS * 2, Wl + gb);
    }
    cp_commit();
}

__global__ __launch_bounds__(256) void mma_gemm(TGemmSet gs)
{
    extern __shared__ __align__(128) __nv_bfloat16 smg[];
    const uint32_t sb = smem_u32(smg);

    const int z = blockIdx.z;
    if (blockIdx.y >= gs.ny[z]) return;
    const __nv_bfloat16* __restrict__ Ah = gs.ah[z];
    const __nv_bfloat16* __restrict__ Al = gs.al[z];
    const __nv_bfloat16* __restrict__ Wh = gs.wh[z];
    const __nv_bfloat16* __restrict__ Wl = gs.wl[z];
    const float* __restrict__ bias = gs.b[z];
    float* __restrict__ C = gs.c[z];

    const int t    = threadIdx.x;
    const int wid  = t >> 5;
    const int lane = t & 31;
    const int wm   = wid >> 2;
    const int wn   = wid & 3;
    const int m0   = blockIdx.y * 128;
    const int n0   = blockIdx.x * 128;

    const int mat = lane >> 3, r = lane & 7;
    int aOff[4], bOff[2];
#pragma unroll
    for (int i = 0; i < 4; i++)
        aOff[i] = (wm * 64 + 16 * i + (mat & 1) * 8 + r) * 40 + (mat >> 1) * 8;
#pragma unroll
    for (int p = 0; p < 2; p++)
        bOff[p] = (wn * 32 + 16 * p + (mat >> 1) * 8 + r) * 40 + (mat & 1) * 8;

    float acc[4][4][4];
#pragma unroll
    for (int i = 0; i < 4; i++)
#pragma unroll
        for (int j = 0; j < 4; j++)
#pragma unroll
            for (int q = 0; q < 4; q++) acc[i][j][q] = 0.f;

    const int NS = DMODEL / 32;
    mg_load_stage(sb, 0, Ah, Al, Wh, Wl, m0, n0, 0,  t);
    mg_load_stage(sb, 1, Ah, Al, Wh, Wl, m0, n0, 32, t);

    for (int s = 0; s < NS; s++) {
        if (s + 1 < NS) cp_wait<1>(); else cp_wait<0>();
        __syncthreads();
        const uint32_t s0 = sb + (s & 1) * STAGE_BYTES;

#pragma unroll
        for (int ks = 0; ks < 2; ks++) {
            const int ke = ks * 16;
            uint32_t ah[4][4], al[4][4], bh[2][4], bl[2][4];
#pragma unroll
            for (int i = 0; i < 4; i++) {
                LDSM_X4(ah[i][0], ah[i][1], ah[i][2], ah[i][3],
                        s0 + (aOff[i] + ke) * 2);
                LDSM_X4(al[i][0], al[i][1], al[i][2], al[i][3],
                        s0 + 1 * SUB_ELEMS * 2 + (aOff[i] + ke) * 2);
            }
#pragma unroll
            for (int p = 0; p < 2; p++) {
                LDSM_X4(bh[p][0], bh[p][1], bh[p][2], bh[p][3],
                        s0 + 2 * SUB_ELEMS * 2 + (bOff[p] + ke) * 2);
                LDSM_X4(bl[p][0], bl[p][1], bl[p][2], bl[p][3],
                        s0 + 3 * SUB_ELEMS * 2 + (bOff[p] + ke) * 2);
            }
#pragma unroll
            for (int i = 0; i < 4; i++)
#pragma unroll
                for (int j = 0; j < 4; j++) {
                    const int p = j >> 1, q = (j & 1) * 2;
                    MMA16816(acc[i][j], ah[i][0], ah[i][1], ah[i][2], ah[i][3],
                             bh[p][q], bh[p][q + 1]);
                    MMA16816(acc[i][j], ah[i][0], ah[i][1], ah[i][2], ah[i][3],
                             bl[p][q], bl[p][q + 1]);
                    MMA16816(acc[i][j], al[i][0], al[i][1], al[i][2], al[i][3],
                             bh[p][q], bh[p][q + 1]);
                }
        }
        __syncthreads();
        if (s + 2 < NS)
            mg_load_stage(sb, s & 1, Ah, Al, Wh, Wl, m0, n0, (s + 2) * 32, t);
    }

    const int r4 = lane >> 2;
    const int c2 = (lane & 3) * 2;
#pragma unroll
    for (int i = 0; i < 4; i++) {
        const int grow = m0 + wm * 64 + 16 * i + r4;
#pragma unroll
        for (int j = 0; j < 4; j++) {
            const int gcol = n0 + wn * 32 + 8 * j + c2;
            const float b0 = bias[gcol], b1 = bias[gcol + 1];
            float2 v0, v1;
            v0.x = acc[i][j][0] + b0; v0.y = acc[i][j][1] + b1;
            v1.x = acc[i][j][2] + b0; v1.y = acc[i][j][3] + b1;
            *(float2*)(C + (size_t)grow * DMODEL + gcol)       = v0;
            *(float2*)(C + (size_t)(grow + 8) * DMODEL + gcol) = v1;
        }
    }
}

// ---------------- RMSNorm + RoPE -> bf16 hi/lo --------------------------------
__global__ void normrope_hl(
    const float* __restrict__ X, int rows,
    const float* __restrict__ w_txt, const float* __restrict__ w_img,
    const float* __restrict__ tcos, const float* __restrict__ tsin,
    const float* __restrict__ icos, const float* __restrict__ isin,
    float outscale,
    __nv_bfloat162* __restrict__ H, __nv_bfloat162* __restrict__ L)
{
    const int id   = blockIdx.x * blockDim.y + threadIdx.y;
    const int lane = threadIdx.x;
    if (id >= rows * NHEAD) return;
    const int row = id / NHEAD;
    const int h   = id % NHEAD;

    const float2* p2 = (const float2*)(X + (size_t)row * DMODEL + h * HD);
    float2 v0 = p2[lane];
    float2 v1 = p2[lane + 32];

    float ss = v0.x * v0.x + v0.y * v0.y + v1.x * v1.x + v1.y * v1.y;
#pragma unroll
    for (int o = 16; o > 0; o >>= 1) ss += __shfl_xor_sync(0xffffffffu, ss, o);
    const float rms = rsqrtf(ss * (1.0f / 128.0f) + 1e-6f);

    const float *w, *cT, *sT;
    if (row < STXT) { w = w_txt; cT = tcos + (size_t)row * 64;          sT = tsin + (size_t)row * 64; }
    else            { w = w_img; cT = icos + (size_t)(row - STXT) * 64; sT = isin + (size_t)(row - STXT) * 64; }

    const size_t ob = ((size_t)row * DMODEL + h * HD) / 2;
#pragma unroll
    for (int half = 0; half < 2; half++) {
        const int p = lane + 32 * half;
        const float2 v = half ? v1 : v0;
        float c = cT[p], s = sT[p];
        float yr = v.x * rms * w[2 * p];
        float yi = v.y * rms * w[2 * p + 1];
        float o0 = (yr * c - yi * s) * outscale;
        float o1 = (yr * s + yi * c) * outscale;
        __nv_bfloat16 h0 = __float2bfloat16(o0);
        __nv_bfloat16 h1 = __float2bfloat16(o1);
        __nv_bfloat16 l0 = __float2bfloat16(o0 - __bfloat162float(h0));
        __nv_bfloat16 l1 = __float2bfloat16(o1 - __bfloat162float(h1));
        H[ob + p] = __nv_bfloat162(h0, h1);
        L[ob + p] = __nv_bfloat162(l0, l1);
    }
}

// ---------------- Flash attention v3: bf16 hi/lo mma.sync --------------------
// 128q x 64kv tiles, 8 warps (16 q rows each), online softmax in registers.
#define AST     136                 // bf16 row stride (272B; 272%128=16 -> conflict-free)
#define AMAT    (64 * AST)          // elems per matrix
#define ASTB    (AMAT * 2)          // bytes per matrix (17408)
#define ASTAGEB (4 * ASTB)          // Kh|Kl|Vh|Vl stage bytes (69632)
#define ATTN3_SMEM (2 * ASTAGEB + 1024)
#define ATHREADS 256

__global__ __launch_bounds__(ATHREADS) void attn3(
    const __nv_bfloat16* __restrict__ Qh, const __nv_bfloat16* __restrict__ Ql,
    const __nv_bfloat16* __restrict__ Kh, const __nv_bfloat16* __restrict__ Kl,
    const __nv_bfloat16* __restrict__ Vh, const __nv_bfloat16* __restrict__ Vl,
    const int* __restrict__ mask,
    __nv_bfloat16* __restrict__ Oh, __nv_bfloat16* __restrict__ Ol)
{
    extern __shared__ __align__(16) char sm3[];
    const uint32_t sbase = smem_u32(sm3);
    float* mb = (float*)(sm3 + 2 * ASTAGEB);

    const int t    = threadIdx.x;
    const int wid  = t >> 5;       // 0..7 -> q rows [wid*16, wid*16+16)
    const int lane = t & 31;
    const int h    = blockIdx.y;
    const int q0   = blockIdx.x * 128;
    const int hcol = h * HD;

    const int gr = lane >> 2, ct = lane & 3;
    const int mat = lane >> 3, r = lane & 7;
    const int bRow = ((mat >> 1) << 3) + r;   // K (non-trans) ldmatrix row sel
    const int bCol = (mat & 1) << 3;
    const int vRow = ((mat & 1) << 3) + r;    // V (trans) ldmatrix row sel
    const int vCol = (mat >> 1) << 3;

    // mask bias
    for (int i = t; i < STXT; i += ATHREADS)
        mb[i] = (mask[i] == 0) ? -1e30f : 0.f;

    // Q fragments (registers, loaded once)
    uint32_t qh[8][4], ql[8][4];
    {
        const size_t r0 = (size_t)(q0 + wid * 16 + gr) * DMODEL + hcol;
        const size_t r1 = r0 + 8 * DMODEL;
#pragma unroll
        for (int c = 0; c < 8; c++) {
            const int col = 16 * c + 2 * ct;
            qh[c][0] = *(const uint32_t*)(Qh + r0 + col);
            qh[c][1] = *(const uint32_t*)(Qh + r1 + col);
            qh[c][2] = *(const uint32_t*)(Qh + r0 + col + 8);
            qh[c][3] = *(const uint32_t*)(Qh + r1 + col + 8);
            ql[c][0] = *(const uint32_t*)(Ql + r0 + col);
            ql[c][1] = *(const uint32_t*)(Ql + r1 + col);
            ql[c][2] = *(const uint32_t*)(Ql + r0 + col + 8);
            ql[c][3] = *(const uint32_t*)(Ql + r1 + col + 8);
        }
    }

    float o[16][4];
#pragma unroll
    for (int j = 0; j < 16; j++)
#pragma unroll
        for (int e = 0; e < 4; e++) o[j][e] = 0.f;
    float m0 = -INFINITY, m1 = -INFINITY, l0 = 0.f, l1 = 0.f;

#define ISSUE_KV3(st, kb)                                                         \
    {                                                                             \
        _Pragma("unroll")                                                         \
        for (int c = t; c < 4096; c += ATHREADS) {                                \
            const int mtx = c >> 10;                                              \
            const int rem = c & 1023;                                             \
            const int row = rem >> 4;                                             \
            const int ch  = (rem & 15) * 8;                                       \
            const __nv_bfloat16* src = (mtx == 0) ? Kh : (mtx == 1) ? Kl          \
                                     : (mtx == 2) ? Vh : Vl;                      \
            cp_async16(sbase + (st) * ASTAGEB + mtx * ASTB + (row * AST + ch) * 2,\
                       src + (size_t)((kb) + row) * DMODEL + hcol + ch);          \
        }                                                                         \
        cp_commit();                                                              \
    }

    const int NT = SKV / 64;   // 68
    ISSUE_KV3(0, 0)

    for (int kt = 0; kt < NT; kt++) {
        const int kb = kt * 64;
        if (kt + 1 < NT) {
            ISSUE_KV3((kt + 1) & 1, (kt + 1) * 64)
            cp_wait<1>();
        } else {
            cp_wait<0>();
        }
        __syncthreads();
        const uint32_t stg = sbase + (kt & 1) * ASTAGEB;

        // ---- QK ----
        float s[8][4];
#pragma unroll
        for (int j = 0; j < 8; j++)
#pragma unroll
            for (int e = 0; e < 4; e++) s[j][e] = 0.f;

#pragma unroll
        for (int c = 0; c < 8; c++) {
#pragma unroll
            for (int g2 = 0; g2 < 4; g2++) {
                uint32_t kh0, kh1, kh2, kh3, kl0, kl1, kl2, kl3;
                const uint32_t a = stg +
                    (((g2 * 16 + bRow) * AST + 16 * c + bCol) << 1);
                LDSM_X4(kh0, kh1, kh2, kh3, a);
                LDSM_X4(kl0, kl1, kl2, kl3, a + ASTB);
                MMA16816(s[2 * g2], qh[c][0], qh[c][1], qh[c][2], qh[c][3], kh0, kh1);
                MMA16816(s[2 * g2], qh[c][0], qh[c][1], qh[c][2], qh[c][3], kl0, kl1);
                MMA16816(s[2 * g2], ql[c][0], ql[c][1], ql[c][2], ql[c][3], kh0, kh1);
                MMA16816(s[2 * g2 + 1], qh[c][0], qh[c][1], qh[c][2], qh[c][3], kh2, kh3);
                MMA16816(s[2 * g2 + 1], qh[c][0], qh[c][1], qh[c][2], qh[c][3], kl2, kl3);
                MMA16816(s[2 * g2 + 1], ql[c][0], ql[c][1], ql[c][2], ql[c][3], kh2, kh3);
            }
        }

        if (kb < STXT) {
#pragma unroll
            for (int j = 0; j < 8; j++) {
                const int col = kb + 8 * j + 2 * ct;
                const float b0 = mb[col], b1 = mb[col + 1];
                s[j][0] += b0; s[j][1] += b1;
                s[j][2] += b0; s[j][3] += b1;
            }
        }

        // ---- online softmax (register-resident) ----
        float tm0 = -1e30f, tm1 = -1e30f;
#pragma unroll
        for (int j = 0; j < 8; j++) {
            tm0 = fmaxf(tm0, fmaxf(s[j][0], s[j][1]));
            tm1 = fmaxf(tm1, fmaxf(s[j][2], s[j][3]));
        }
        tm0 = fmaxf(tm0, __shfl_xor_sync(0xffffffffu, tm0, 1));
        tm0 = fmaxf(tm0, __shfl_xor_sync(0xffffffffu, tm0, 2));
        tm1 = fmaxf(tm1, __shfl_xor_sync(0xffffffffu, tm1, 1));
        tm1 = fmaxf(tm1, __shfl_xor_sync(0xffffffffu, tm1, 2));
        const float mn0 = fmaxf(m0, tm0), mn1 = fmaxf(m1, tm1);
        const float c0 = __expf(m0 - mn0), c1 = __expf(m1 - mn1);
        l0 *= c0; l1 *= c1;
#pragma unroll
        for (int j = 0; j < 16; j++) {
            o[j][0] *= c0; o[j][1] *= c0;
            o[j][2] *= c1; o[j][3] *= c1;
        }
        float s0 = 0.f, s1 = 0.f;
#pragma unroll
        for (int j = 0; j < 8; j++) {
            s[j][0] = __expf(s[j][0] - mn0);
            s[j][1] = __expf(s[j][1] - mn0);
            s[j][2] = __expf(s[j][2] - mn1);
            s[j][3] = __expf(s[j][3] - mn1);
            s0 += s[j][0] + s[j][1];
            s1 += s[j][2] + s[j][3];
        }
        s0 += __shfl_xor_sync(0xffffffffu, s0, 1);
        s0 += __shfl_xor_sync(0xffffffffu, s0, 2);
        s1 += __shfl_xor_sync(0xffffffffu, s1, 1);
        s1 += __shfl_xor_sync(0xffffffffu, s1, 2);
        l0 += s0; l1 += s1;
        m0 = mn0; m1 = mn1;

        // ---- pack P to bf16 hi/lo A-fragments ----
        uint32_t ph[4][4], pl[4][4];
#pragma unroll
        for (int mm = 0; mm < 4; mm++) {
            const int j0 = 2 * mm, j1 = 2 * mm + 1;
            ph[mm][0] = packbf(s[j0][0], s[j0][1]);
            ph[mm][1] = packbf(s[j0][2], s[j0][3]);
            ph[mm][2] = packbf(s[j1][0], s[j1][1]);
            ph[mm][3] = packbf(s[j1][2], s[j1][3]);
            pl[mm][0] = packbf(s[j0][0] - bfhi(s[j0][0]), s[j0][1] - bfhi(s[j0][1]));
            pl[mm][1] = packbf(s[j0][2] - bfhi(s[j0][2]), s[j0][3] - bfhi(s[j0][3]));
            pl[mm][2] = packbf(s[j1][0] - bfhi(s[j1][0]), s[j1][1] - bfhi(s[j1][1]));
            pl[mm][3] = packbf(s[j1][2] - bfhi(s[j1][2]), s[j1][3] - bfhi(s[j1][3]));
        }

        // ---- PV ----
#pragma unroll
        for (int mm = 0; mm < 4; mm++) {
#pragma unroll
            for (int g = 0; g < 8; g++) {
                uint32_t vh0, vh1, vh2, vh3, vl0, vl1, vl2, vl3;
                const uint32_t a = stg + 2 * ASTB +
                    (((16 * mm + vRow) * AST + 16 * g + vCol) << 1);
                LDSM_X4_T(vh0, vh1, vh2, vh3, a);
                LDSM_X4_T(vl0, vl1, vl2, vl3, a + ASTB);
                MMA16816(o[2 * g], ph[mm][0], ph[mm][1], ph[mm][2], ph[mm][3], vh0, vh1);
                MMA16816(o[2 * g], ph[mm][0], ph[mm][1], ph[mm][2], ph[mm][3], vl0, vl1);
                MMA16816(o[2 * g], pl[mm][0], pl[mm][1], pl[mm][2], pl[mm][3], vh0, vh1);
                MMA16816(o[2 * g + 1], ph[mm][0], ph[mm][1], ph[mm][2], ph[mm][3], vh2, vh3);
                MMA16816(o[2 * g + 1], ph[mm][0], ph[mm][1], ph[mm][2], ph[mm][3], vl2, vl3);
                MMA16816(o[2 * g + 1], pl[mm][0], pl[mm][1], pl[mm][2], pl[mm][3], vh2, vh3);
            }
        }
        __syncthreads();
    }
#undef ISSUE_KV3

    // ---- epilogue: O /= l, write bf16 hi/lo ----
    const float inv0 = 1.0f / l0, inv1 = 1.0f / l1;
    const size_t r0 = (size_t)(q0 + wid * 16 + gr) * DMODEL + hcol;
    const size_t r1 = r0 + 8 * DMODEL;
#pragma unroll
    for (int j = 0; j < 16; j++) {
        const int col = 8 * j + 2 * ct;
        const float f0 = o[j][0] * inv0, f1 = o[j][1] * inv0;
        const float f2 = o[j][2] * inv1, f3 = o[j][3] * inv1;
        *(uint32_t*)(Oh + r0 + col) = packbf(bfhi(f0), bfhi(f1));
        *(uint32_t*)(Ol + r0 + col) = packbf(f0 - bfhi(f0), f1 - bfhi(f1));
        *(uint32_t*)(Oh + r1 + col) = packbf(bfhi(f2), bfhi(f3));
        *(uint32_t*)(Ol + r1 + col) = packbf(f2 - bfhi(f2), f3 - bfhi(f3));
    }
}

// ---------------- launch -----------------------------------------------------
extern "C" void kernel_launch(void* const* d_in, const int* in_sizes, int n_in,
                              void* d_out, int out_size)
{
    const float* hidden = (const float*)d_in[0];
    const float* enc    = (const float*)d_in[1];
    const int*   mask   = (const int*)  d_in[2];
    const float* ck     = (const float*)d_in[3];
    const float* cv     = (const float*)d_in[4];
    const float* icos   = (const float*)d_in[5];
    const float* isin   = (const float*)d_in[6];
    const float* tcos   = (const float*)d_in[7];
    const float* tsin   = (const float*)d_in[8];
    const float* Wq     = (const float*)d_in[9];
    const float* bq     = (const float*)d_in[10];
    const float* Wk     = (const float*)d_in[11];
    const float* bk     = (const float*)d_in[12];
    const float* Wv     = (const float*)d_in[13];
    const float* bv     = (const float*)d_in[14];
    const float* Wq_add = (const float*)d_in[15];
    const float* bq_add = (const float*)d_in[16];
    const float* Wk_add = (const float*)d_in[17];
    const float* bk_add = (const float*)d_in[18];
    const float* Wv_add = (const float*)d_in[19];
    const float* bv_add = (const float*)d_in[20];
    const float* nqw    = (const float*)d_in[21];
    const float* nkw    = (const float*)d_in[22];
    const float* naqw   = (const float*)d_in[23];
    const float* nakw   = (const float*)d_in[24];
    const float* Wo     = (const float*)d_in[25];
    const float* bo     = (const float*)d_in[26];
    const float* Wo_add = (const float*)d_in[27];
    const float* bo_add = (const float*)d_in[28];
    float* out = (float*)d_out;

    float *Qb, *Kb, *Vb;
    cudaGetSymbolAddress((void**)&Qb, g_Q);
    cudaGetSymbolAddress((void**)&Kb, g_K);
    cudaGetSymbolAddress((void**)&Vb, g_V);
    __nv_bfloat16 *WhT, *WlT, *Ah, *Al, *Eh, *El, *Khb, *Klb, *Vhb, *Vlb;
    cudaGetSymbolAddress((void**)&WhT, g_WhT);
    cudaGetSymbolAddress((void**)&WlT, g_WlT);
    cudaGetSymbolAddress((void**)&Ah, g_Ah);
    cudaGetSymbolAddress((void**)&Al, g_Al);
    cudaGetSymbolAddress((void**)&Eh, g_Eh);
    cudaGetSymbolAddress((void**)&El, g_El);
    cudaGetSymbolAddress((void**)&Khb, g_Kh);
    cudaGetSymbolAddress((void**)&Klb, g_Kl);
    cudaGetSymbolAddress((void**)&Vhb, g_Vh);
    cudaGetSymbolAddress((void**)&Vlb, g_Vl);

    cudaFuncSetAttribute(mma_gemm, cudaFuncAttributeMaxDynamicSharedMemorySize,
                         MG_SMEM);
    cudaFuncSetAttribute(attn3, cudaFuncAttributeMaxDynamicSharedMemorySize,
                         ATTN3_SMEM);

    // cached K -> tail of fp32 K buffer (rows 1280..4351); V handled via convert
    cudaMemcpyAsync(Kb + (size_t)1280 * DMODEL, ck,
                    (size_t)3072 * DMODEL * sizeof(float), cudaMemcpyDeviceToDevice);

    // weight split+transpose
    {
        WSrc ws;
        ws.p[0] = Wq;     ws.p[1] = Wk;     ws.p[2] = Wv;
        ws.p[3] = Wq_add; ws.p[4] = Wk_add; ws.p[5] = Wv_add;
        ws.p[6] = Wo;     ws.p[7] = Wo_add;
        convert_hl_T<<<dim3(96, 96, 8), dim3(32, 8)>>>(ws, WhT, WlT);
    }
    // activation splits
    {
        int n4h = 1024 * DMODEL / 4;
        convert_hl<<<(n4h + 255) / 256, 256>>>((const float4*)hidden,
                                               (__nv_bfloat162*)Ah, (__nv_bfloat162*)Al, n4h);
        int n4e = STXT * DMODEL / 4;
        convert_hl<<<(n4e + 255) / 256, 256>>>((const float4*)enc,
                                               (__nv_bfloat162*)Eh, (__nv_bfloat162*)El, n4e);
    }

    // QKV projections: ONE launch, z=0..2 img (8 y-tiles), z=3..5 txt (2 y-tiles)
    {
        TGemmSet g;
        for (int z = 0; z < 3; z++) {
            g.ah[z] = Ah; g.al[z] = Al;
            g.wh[z] = WhT + (size_t)z * WELEMS;
            g.wl[z] = WlT + (size_t)z * WELEMS;
            g.ny[z] = 8;
            g.ah[z + 3] = Eh; g.al[z + 3] = El;
            g.wh[z + 3] = WhT + (size_t)(z + 3) * WELEMS;
            g.wl[z + 3] = WlT + (size_t)(z + 3) * WELEMS;
            g.ny[z + 3] = 2;
        }
        g.b[0] = bq; g.b[1] = bk; g.b[2] = bv;
        g.b[3] = bq_add; g.b[4] = bk_add; g.b[5] = bv_add;
        g.c[0] = Qb + (size_t)256 * DMODEL;
        g.c[1] = Kb + (size_t)256 * DMODEL;
        g.c[2] = Vb + (size_t)256 * DMODEL;
        g.c[3] = Qb; g.c[4] = Kb; g.c[5] = Vb;
        mma_gemm<<<dim3(24, 8, 6), 256, MG_SMEM>>>(g);
    }

    // RMSNorm + RoPE -> bf16 hi/lo (Q into Ah/Al — GEMM inputs are dead now)
    const float qscale = 0.08838834764831845f; // 1/sqrt(128)
    dim3 nb(32, 8);
    {
        int tot = LQ * NHEAD;
        normrope_hl<<<(tot + 7) / 8, nb>>>(Qb, LQ, naqw, nqw,
                                           tcos, tsin, icos, isin, qscale,
                                           (__nv_bfloat162*)Ah, (__nv_bfloat162*)Al);
    }
    {
        int tot = SKV * NHEAD;
        normrope_hl<<<(tot + 7) / 8, nb>>>(Kb, SKV, nakw, nkw,
                                           tcos, tsin, icos, isin, 1.0f,
                                           (__nv_bfloat162*)Khb, (__nv_bfloat162*)Klb);
    }
    // V hi/lo: projected rows 0..1279 + cached rows 1280..4351
    {
        int n4v = 1280 * DMODEL / 4;
        convert_hl<<<(n4v + 255) / 256, 256>>>((const float4*)Vb,
                                               (__nv_bfloat162*)Vhb, (__nv_bfloat162*)Vlb, n4v);
        int n4c = 3072 * DMODEL / 4;
        convert_hl<<<(n4c + 255) / 256, 256>>>((const float4*)cv,
                                               (__nv_bfloat162*)(Vhb + (size_t)1280 * DMODEL),
                                               (__nv_bfloat162*)(Vlb + (size_t)1280 * DMODEL), n4c);
    }

    // attention: reads Q from Ah/Al, writes O (bf16 hi/lo) back into Ah/Al
    attn3<<<dim3(LQ / 128, NHEAD), ATHREADS, ATTN3_SMEM>>>(
        Ah, Al, Khb, Klb, Vhb, Vlb, mask, Ah, Al);

    // output projections: ONE launch, z=0 img (8 y-tiles), z=1 txt (2 y-tiles)
    {
        TGemmSet g;
        g.ah[0] = Ah + (size_t)256 * DMODEL; g.al[0] = Al + (size_t)256 * DMODEL;
        g.wh[0] = WhT + 6 * WELEMS;          g.wl[0] = WlT + 6 * WELEMS;
        g.b[0]  = bo;                        g.c[0]  = out;
        g.ny[0] = 8;
        g.ah[1] = Ah;                        g.al[1] = Al;
        g.wh[1] = WhT + 7 * WELEMS;          g.wl[1] = WlT + 7 * WELEMS;
        g.b[1]  = bo_add;                    g.c[1]  = out + (size_t)1024 * DMODEL;
        g.ny[1] = 2;
        for (int z = 2; z < 6; z++) {
            g.ah[z] = Ah; g.al[z] = Al;
            g.wh[z] = WhT; g.wl[z] = WlT;
            g.b[z] = bo; g.c[z] = out; g.ny[z] = 0;
        }
        mma_gemm<<<dim3(24, 8, 2), 256, MG_SMEM>>>(g);
    }
}